// round 1
// baseline (speedup 1.0000x reference)
#include <cuda_runtime.h>

#define Bq 4
#define Cc 512
#define Hd 96
#define Wd 96
#define NPIX 9216
#define ICd 128
#define QCd 16

// ---------------- scratch (static device allocations) ----------------
__device__ float g_out1[Bq * ICd * NPIX];            // after conva+bn1+relu
__device__ float g_q[Bq * QCd * NPIX];
__device__ float g_k[Bq * QCd * NPIX];
__device__ float g_v[Bq * ICd * NPIX];
__device__ float g_cca[Bq * ICd * NPIX];             // cca output
__device__ float g_out2[Bq * ICd * NPIX];            // after convb+bn2+relu
__device__ float g_bott1[(size_t)Bq * Cc * NPIX];    // after bot conv1+bn3+relu
__device__ float g_bott2[(size_t)Bq * Cc * NPIX];    // after bot conv2+bias
__device__ float g_energy[Bq * Cc * Cc];             // CAM energy / attention

__device__ __forceinline__ float* wbuf(int id) {
    switch (id) {
        case 0: return g_out1;
        case 1: return g_q;
        case 2: return g_k;
        case 3: return g_v;
        case 4: return g_cca;
        case 5: return g_out2;
        case 6: return g_bott1;
        case 7: return g_bott2;
        case 8: return g_energy;
    }
    return nullptr;
}
__device__ __forceinline__ const float* cbuf(int id, const float* ext) {
    if (id < 0) return ext;
    return wbuf(id);
}

// ---------------- direct conv3x3 + BN + ReLU ----------------
// Block: 256 threads = 16x16 spatial tile; OCPT output channels per block.
// Input channels streamed in chunks of 8 through shared memory.
#define OCPT 16

__global__ void __launch_bounds__(256) conv3x3_bn_relu(
    const float* __restrict__ in1e, int in1_id, int cin1,
    const float* __restrict__ in2e, int in2_id, int cin2,
    const float* __restrict__ wgt,
    const float* __restrict__ bns, const float* __restrict__ bnb,
    const float* __restrict__ bnm, const float* __restrict__ bnv,
    int out_id, int OC)
{
    const float* pin1 = cbuf(in1_id, in1e);
    const float* pin2 = cbuf(in2_id, in2e);
    float* out = wbuf(out_id);
    const int CIN = cin1 + cin2;

    int tile = blockIdx.x;
    int tx0 = (tile % 6) * 16;
    int ty0 = (tile / 6) * 16;
    int ocb = blockIdx.y * OCPT;
    int b = blockIdx.z;
    int tx = threadIdx.x & 15;
    int ty = threadIdx.x >> 4;

    __shared__ float ti[8][324];        // 8 ic x 18x18 padded tile
    __shared__ float tw[OCPT][8][12];   // weights, 9 taps padded to 12 (float4)

    float acc[OCPT];
#pragma unroll
    for (int o = 0; o < OCPT; o++) acc[o] = 0.f;

    for (int icc = 0; icc < CIN; icc += 8) {
        __syncthreads();
        // load input chunk (zero padded at borders)
        for (int idx = threadIdx.x; idx < 8 * 324; idx += 256) {
            int ic = idx / 324;
            int rem = idx - ic * 324;
            int r = rem / 18;
            int cl = rem - r * 18;
            int gh = ty0 - 1 + r;
            int gw = tx0 - 1 + cl;
            float val = 0.f;
            if ((unsigned)gh < (unsigned)Hd && (unsigned)gw < (unsigned)Wd) {
                int gic = icc + ic;
                const float* src = (gic < cin1)
                    ? pin1 + ((size_t)b * cin1 + gic) * NPIX
                    : pin2 + ((size_t)b * cin2 + (gic - cin1)) * NPIX;
                val = src[gh * Wd + gw];
            }
            ti[ic][rem] = val;
        }
        // load weight chunk
        for (int idx = threadIdx.x; idx < OCPT * 8 * 9; idx += 256) {
            int o = idx / 72;
            int rem = idx - o * 72;
            int ic = rem / 9;
            int t9 = rem - ic * 9;
            tw[o][ic][t9] = wgt[((size_t)(ocb + o) * CIN + icc + ic) * 9 + t9];
        }
        __syncthreads();
#pragma unroll
        for (int ic = 0; ic < 8; ic++) {
            const float* tr = &ti[ic][ty * 18 + tx];
            float x00 = tr[0],  x01 = tr[1],  x02 = tr[2];
            float x10 = tr[18], x11 = tr[19], x12 = tr[20];
            float x20 = tr[36], x21 = tr[37], x22 = tr[38];
#pragma unroll
            for (int o = 0; o < OCPT; o++) {
                const float4* wp = (const float4*)tw[o][ic];
                float4 wa = wp[0];
                float4 wb = wp[1];
                float w8 = tw[o][ic][8];
                acc[o] += x00 * wa.x + x01 * wa.y + x02 * wa.z
                        + x10 * wa.w + x11 * wb.x + x12 * wb.y
                        + x20 * wb.z + x21 * wb.w + x22 * w8;
            }
        }
    }
    int oh = ty0 + ty, ow = tx0 + tx;
#pragma unroll
    for (int o = 0; o < OCPT; o++) {
        int oc = ocb + o;
        float inv = bns[oc] * rsqrtf(bnv[oc] + 1e-5f);
        float r = acc[o] * inv + (bnb[oc] - bnm[oc] * inv);
        out[((size_t)b * OC + oc) * NPIX + oh * Wd + ow] = fmaxf(r, 0.f);
    }
}

// ---------------- fused q/k/v 1x1 convs (from g_out1) ----------------
__global__ void __launch_bounds__(128) qkv_kernel(
    const float* __restrict__ wq, const float* __restrict__ bq,
    const float* __restrict__ wk, const float* __restrict__ bk,
    const float* __restrict__ wv, const float* __restrict__ bv)
{
    int b = blockIdx.y;
    int px0 = blockIdx.x * 64;
    int t = threadIdx.x;
    int px = t & 63;
    int half = t >> 6;

    __shared__ float xs[128][64];
    for (int idx = t; idx < 128 * 64; idx += 128) {
        int ic = idx >> 6;
        int p = idx & 63;
        xs[ic][p] = g_out1[((size_t)b * ICd + ic) * NPIX + px0 + p];
    }
    __syncthreads();

    for (int oc = half * 80; oc < half * 80 + 80; oc++) {
        const float* wrow;
        float bias;
        float* dst;
        if (oc < 16) {
            wrow = wq + oc * 128; bias = bq[oc];
            dst = g_q + ((size_t)b * QCd + oc) * NPIX;
        } else if (oc < 32) {
            int o = oc - 16;
            wrow = wk + o * 128; bias = bk[o];
            dst = g_k + ((size_t)b * QCd + o) * NPIX;
        } else {
            int o = oc - 32;
            wrow = wv + o * 128; bias = bv[o];
            dst = g_v + ((size_t)b * ICd + o) * NPIX;
        }
        float a = bias;
#pragma unroll 8
        for (int ic = 0; ic < 128; ic += 4) {
            float4 w4 = *(const float4*)(wrow + ic);
            a += w4.x * xs[ic][px] + w4.y * xs[ic + 1][px]
               + w4.z * xs[ic + 2][px] + w4.w * xs[ic + 3][px];
        }
        dst[px0 + px] = a;
    }
}

// ---------------- criss-cross attention: one block per (b,h,w) ----------------
__global__ void __launch_bounds__(128) cca_kernel(const float* __restrict__ gamma)
{
    int w = blockIdx.x, h = blockIdx.y, b = blockIdx.z;
    int t = threadIdx.x;

    __shared__ float qv[16];
    __shared__ float e[192];
    __shared__ float red[4];

    if (t < 16) qv[t] = g_q[((size_t)b * QCd + t) * NPIX + h * Wd + w];
    __syncthreads();

    if (t < 96) {
        float aH = 0.f, aW = 0.f;
        const float* kH = g_k + (size_t)b * QCd * NPIX + t * Wd + w;
        const float* kW = g_k + (size_t)b * QCd * NPIX + h * Wd + t;
#pragma unroll
        for (int c = 0; c < 16; c++) {
            float qc = qv[c];
            aH += qc * kH[c * NPIX];
            aW += qc * kW[c * NPIX];
        }
        e[t] = (t == h) ? -1e30f : aH;
        e[96 + t] = aW;
    }
    __syncthreads();

    // block max over 192
    float lm = -1e30f;
    for (int i = t; i < 192; i += 128) lm = fmaxf(lm, e[i]);
#pragma unroll
    for (int o = 16; o; o >>= 1) lm = fmaxf(lm, __shfl_xor_sync(0xffffffffu, lm, o));
    if ((t & 31) == 0) red[t >> 5] = lm;
    __syncthreads();
    float M = fmaxf(fmaxf(red[0], red[1]), fmaxf(red[2], red[3]));
    __syncthreads();

    // exp + sum
    float ls = 0.f;
    for (int i = t; i < 192; i += 128) {
        float p = __expf(e[i] - M);
        e[i] = p;
        ls += p;
    }
#pragma unroll
    for (int o = 16; o; o >>= 1) ls += __shfl_xor_sync(0xffffffffu, ls, o);
    if ((t & 31) == 0) red[t >> 5] = ls;
    __syncthreads();
    float S = red[0] + red[1] + red[2] + red[3];
    float rinv = 1.f / S;

    // output: thread t = channel
    const float* vH = g_v + ((size_t)b * ICd + t) * NPIX + w;
    const float* vW = g_v + ((size_t)b * ICd + t) * NPIX + h * Wd;
    float oH = 0.f, oW = 0.f;
#pragma unroll 4
    for (int s = 0; s < 96; s++) {
        oH += vH[s * Wd] * e[s];
        oW += vW[s] * e[96 + s];
    }
    size_t idx = ((size_t)b * ICd + t) * NPIX + h * Wd + w;
    float g = __ldg(gamma);
    g_cca[idx] = g * (oH + oW) * rinv + g_out1[idx];
}

// ---------------- CAM softmax over energy rows ----------------
// softmax(max - e) == exp(min - e) / sum(exp(min - e)); only a min-reduce needed.
__global__ void __launch_bounds__(128) cam_softmax_kernel()
{
    int b = blockIdx.y, c = blockIdx.x;
    float* row = g_energy + ((size_t)b * Cc + c) * Cc;
    int t = threadIdx.x;
    __shared__ float red[4];

    float lmn = 1e30f;
    for (int i = t; i < Cc; i += 128) lmn = fminf(lmn, row[i]);
#pragma unroll
    for (int o = 16; o; o >>= 1) lmn = fminf(lmn, __shfl_xor_sync(0xffffffffu, lmn, o));
    if ((t & 31) == 0) red[t >> 5] = lmn;
    __syncthreads();
    float mn = fminf(fminf(red[0], red[1]), fminf(red[2], red[3]));
    __syncthreads();

    float ls = 0.f;
    for (int i = t; i < Cc; i += 128) {
        float p = __expf(mn - row[i]);
        row[i] = p;
        ls += p;
    }
#pragma unroll
    for (int o = 16; o; o >>= 1) ls += __shfl_xor_sync(0xffffffffu, ls, o);
    if ((t & 31) == 0) red[t >> 5] = ls;
    __syncthreads();
    float S = red[0] + red[1] + red[2] + red[3];
    float inv = 1.f / S;
    for (int i = t; i < Cc; i += 128) row[i] *= inv;
}

// ---------------- tiled fp32 GEMM, 64x64 tile, 4x4 per thread ----------------
// MODE 0: C = A*B'   (energy, BT=true)
// MODE 1: C = A*B + bias[row]           (bot conv2 1x1)
// MODE 2: C = g_bott2 + gamma*(A*B) + x (final output, fully overwrites d_out)
template<int MODE, bool BT>
__global__ void __launch_bounds__(256) sgemm_kernel(
    const float* __restrict__ Aex, int A_id, size_t sAb,
    const float* __restrict__ Bex, int B_id, size_t sBb,
    float* __restrict__ Cex, int C_id, size_t sCb,
    int M, int Nn, int K,
    const float* __restrict__ bias,
    const float* __restrict__ addx,
    const float* __restrict__ gamma)
{
    int bz = blockIdx.z;
    const float* A = cbuf(A_id, Aex) + (size_t)bz * sAb;
    const float* Bm = cbuf(B_id, Bex) + (size_t)bz * sBb;
    float* Cm = (C_id >= 0 ? wbuf(C_id) : Cex) + (size_t)bz * sCb;

    __shared__ float As[16][65];
    __shared__ float Bs[16][65];

    int tid = threadIdx.x;
    int tx = tid & 15, ty = tid >> 4;
    int row0 = blockIdx.y * 64, col0 = blockIdx.x * 64;

    float acc[4][4];
#pragma unroll
    for (int i = 0; i < 4; i++)
#pragma unroll
        for (int j = 0; j < 4; j++) acc[i][j] = 0.f;

    for (int k0 = 0; k0 < K; k0 += 16) {
#pragma unroll
        for (int i = 0; i < 4; i++) {
            int idx = tid + i * 256;
            int kk = idx & 15, r = idx >> 4;
            As[kk][r] = A[(size_t)(row0 + r) * K + k0 + kk];
        }
        if (BT) {
#pragma unroll
            for (int i = 0; i < 4; i++) {
                int idx = tid + i * 256;
                int kk = idx & 15, cI = idx >> 4;
                Bs[kk][cI] = Bm[(size_t)(col0 + cI) * K + k0 + kk];
            }
        } else {
#pragma unroll
            for (int i = 0; i < 4; i++) {
                int idx = tid + i * 256;
                int cI = idx & 63, kk = idx >> 6;
                Bs[kk][cI] = Bm[(size_t)(k0 + kk) * Nn + col0 + cI];
            }
        }
        __syncthreads();
#pragma unroll
        for (int kk = 0; kk < 16; kk++) {
            float a0 = As[kk][ty * 4 + 0], a1 = As[kk][ty * 4 + 1];
            float a2 = As[kk][ty * 4 + 2], a3 = As[kk][ty * 4 + 3];
            float b0 = Bs[kk][tx * 4 + 0], b1 = Bs[kk][tx * 4 + 1];
            float b2 = Bs[kk][tx * 4 + 2], b3 = Bs[kk][tx * 4 + 3];
            acc[0][0] += a0 * b0; acc[0][1] += a0 * b1; acc[0][2] += a0 * b2; acc[0][3] += a0 * b3;
            acc[1][0] += a1 * b0; acc[1][1] += a1 * b1; acc[1][2] += a1 * b2; acc[1][3] += a1 * b3;
            acc[2][0] += a2 * b0; acc[2][1] += a2 * b1; acc[2][2] += a2 * b2; acc[2][3] += a2 * b3;
            acc[3][0] += a3 * b0; acc[3][1] += a3 * b1; acc[3][2] += a3 * b2; acc[3][3] += a3 * b3;
        }
        __syncthreads();
    }

    float g = (MODE == 2) ? __ldg(gamma) : 0.f;
#pragma unroll
    for (int i = 0; i < 4; i++) {
        int r = row0 + ty * 4 + i;
#pragma unroll
        for (int j = 0; j < 4; j++) {
            int cI = col0 + tx * 4 + j;
            size_t off = (size_t)r * Nn + cI;
            float vacc = acc[i][j];
            if (MODE == 0) {
                Cm[off] = vacc;
            } else if (MODE == 1) {
                Cm[off] = vacc + __ldg(&bias[r]);
            } else {
                const float* bt = g_bott2 + (size_t)bz * sCb;
                const float* xx = addx + (size_t)bz * sCb;
                Cm[off] = bt[off] + g * vacc + xx[off];
            }
        }
    }
}

// ---------------- launch ----------------
extern "C" void kernel_launch(void* const* d_in, const int* in_sizes, int n_in,
                              void* d_out, int out_size)
{
    const float* x        = (const float*)d_in[0];
    const float* conva_w  = (const float*)d_in[1];
    const float* bn1_s    = (const float*)d_in[2];
    const float* bn1_b    = (const float*)d_in[3];
    const float* bn1_m    = (const float*)d_in[4];
    const float* bn1_v    = (const float*)d_in[5];
    const float* wq       = (const float*)d_in[6];
    const float* bq       = (const float*)d_in[7];
    const float* wk       = (const float*)d_in[8];
    const float* bk       = (const float*)d_in[9];
    const float* wv       = (const float*)d_in[10];
    const float* bv       = (const float*)d_in[11];
    const float* gamma_cca= (const float*)d_in[12];
    const float* convb_w  = (const float*)d_in[13];
    const float* bn2_s    = (const float*)d_in[14];
    const float* bn2_b    = (const float*)d_in[15];
    const float* bn2_m    = (const float*)d_in[16];
    const float* bn2_v    = (const float*)d_in[17];
    const float* bot_w1   = (const float*)d_in[18];
    const float* bn3_s    = (const float*)d_in[19];
    const float* bn3_b    = (const float*)d_in[20];
    const float* bn3_m    = (const float*)d_in[21];
    const float* bn3_v    = (const float*)d_in[22];
    const float* bot_w2   = (const float*)d_in[23];
    const float* bot_b2   = (const float*)d_in[24];
    const float* gamma_cam= (const float*)d_in[25];
    float* out = (float*)d_out;

    const size_t sCN = (size_t)Cc * NPIX;   // 512*9216
    const size_t sCC = (size_t)Cc * Cc;     // 512*512

    // 1) conva: 512 -> 128, bn1, relu -> g_out1 (id 0)
    conv3x3_bn_relu<<<dim3(36, ICd / OCPT, Bq), 256>>>(
        x, -1, Cc, nullptr, -1, 0, conva_w,
        bn1_s, bn1_b, bn1_m, bn1_v, 0, ICd);

    // 2) q/k/v 1x1 convs
    qkv_kernel<<<dim3(NPIX / 64, Bq), 128>>>(wq, bq, wk, bk, wv, bv);

    // 3) criss-cross attention -> g_cca (id 4)
    cca_kernel<<<dim3(Wd, Hd, Bq), 128>>>(gamma_cca);

    // 4) convb: 128 -> 128, bn2, relu -> g_out2 (id 5)
    conv3x3_bn_relu<<<dim3(36, ICd / OCPT, Bq), 256>>>(
        nullptr, 4, ICd, nullptr, -1, 0, convb_w,
        bn2_s, bn2_b, bn2_m, bn2_v, 5, ICd);

    // 5) bot conv1 on concat(x, out2): 640 -> 512, bn3, relu -> g_bott1 (id 6)
    conv3x3_bn_relu<<<dim3(36, Cc / OCPT, Bq), 256>>>(
        x, -1, Cc, nullptr, 5, ICd, bot_w1,
        bn3_s, bn3_b, bn3_m, bn3_v, 6, Cc);

    // 6) bot conv2 (1x1) + bias: g_bott2 = W2 @ bott1 + b2  (id 7)
    sgemm_kernel<1, false><<<dim3(NPIX / 64, Cc / 64, Bq), 256>>>(
        bot_w2, -1, 0,
        nullptr, 6, sCN,
        nullptr, 7, sCN,
        Cc, NPIX, Cc,
        bot_b2, nullptr, nullptr);

    // 7) CAM energy: x @ x^T per batch -> g_energy (id 8)
    sgemm_kernel<0, true><<<dim3(Cc / 64, Cc / 64, Bq), 256>>>(
        x, -1, sCN,
        x, -1, sCN,
        nullptr, 8, sCC,
        Cc, Cc, NPIX,
        nullptr, nullptr, nullptr);

    // 8) CAM softmax (in place on g_energy)
    cam_softmax_kernel<<<dim3(Cc, Bq), 128>>>();

    // 9) final: out = bott2 + gamma_cam * (att @ x) + x
    sgemm_kernel<2, false><<<dim3(NPIX / 64, Cc / 64, Bq), 256>>>(
        nullptr, 8, sCC,
        x, -1, sCN,
        out, -1, sCN,
        Cc, NPIX, Cc,
        nullptr, x, gamma_cam);
}

// round 2
// speedup vs baseline: 1.8234x; 1.8234x over previous
#include <cuda_runtime.h>

#define Bq 4
#define Cc 512
#define Hd 96
#define Wd 96
#define NPIX 9216
#define ICd 128
#define QCd 16
#define KSPLIT 6
#define ECHUNK 1536

// ---------------- scratch (static device allocations) ----------------
__device__ float g_out1[Bq * ICd * NPIX];
__device__ float g_q[Bq * QCd * NPIX];
__device__ float g_k[Bq * QCd * NPIX];
__device__ float g_v[Bq * ICd * NPIX];
__device__ float g_cca[Bq * ICd * NPIX];
__device__ float g_out2[Bq * ICd * NPIX];
__device__ float g_bott1[(size_t)Bq * Cc * NPIX];
__device__ float g_bott2[(size_t)Bq * Cc * NPIX];
__device__ float g_energy[Bq * Cc * Cc];
__device__ float g_wa[512 * 9 * 128];
__device__ float g_wb[128 * 9 * 128];
__device__ float g_w1[640 * 9 * 512];
__device__ float g_epart[(size_t)KSPLIT * Bq * Cc * Cc];

__device__ __forceinline__ float* wbuf(int id) {
    switch (id) {
        case 0: return g_out1;
        case 1: return g_q;
        case 2: return g_k;
        case 3: return g_v;
        case 4: return g_cca;
        case 5: return g_out2;
        case 6: return g_bott1;
        case 7: return g_bott2;
        case 8: return g_energy;
        case 9: return g_wa;
        case 10: return g_wb;
        case 11: return g_w1;
        case 12: return g_epart;
    }
    return nullptr;
}
__device__ __forceinline__ const float* cbuf(int id, const float* ext) {
    if (id < 0) return ext;
    return wbuf(id);
}

// ---------------- weight transpose: w[oc][ic][9] -> wt[(ic*9+tap)][oc] ----------------
__global__ void wtrans_kernel(const float* __restrict__ src, int dst_id, int CIN, int OC)
{
    float* dst = wbuf(dst_id);
    int n = OC * CIN * 9;
    for (int i = blockIdx.x * blockDim.x + threadIdx.x; i < n; i += gridDim.x * blockDim.x) {
        int oc = i / (CIN * 9);
        int rem = i - oc * (CIN * 9);   // ic*9+tap
        dst[rem * OC + oc] = src[i];
    }
}

// ---------------- conv3x3 + BN + ReLU, 64oc x 16x16 tile, 8oc x 8pix per thread ----------------
__global__ void __launch_bounds__(256) conv3x3_v2(
    const float* __restrict__ in1e, int in1_id, int cin1,
    int in2_id, int cin2,
    int wt_id,
    const float* __restrict__ bns, const float* __restrict__ bnb,
    const float* __restrict__ bnm, const float* __restrict__ bnv,
    int out_id, int OC)
{
    const float* pin1 = cbuf(in1_id, in1e);
    const float* pin2 = (in2_id >= 0) ? wbuf(in2_id) : nullptr;
    const float* wt = wbuf(wt_id);
    float* out = wbuf(out_id);
    const int CIN = cin1 + cin2;

    int tile = blockIdx.x;
    int tx0 = (tile % 6) * 16;
    int ty0 = (tile / 6) * 16;
    int ocb = blockIdx.y * 64;
    int b = blockIdx.z;
    int tid = threadIdx.x;
    int ocg = tid >> 5;
    int lane = tid & 31;
    int px = (lane & 3) * 4;
    int py = (lane >> 2) * 2;

    __shared__ float ti[8][324];     // 8 ic x 18x18
    __shared__ float tw[72][64];     // [(ic,tap)][oc]

    float acc[8][8];
#pragma unroll
    for (int o = 0; o < 8; o++)
#pragma unroll
        for (int p = 0; p < 8; p++) acc[o][p] = 0.f;

    for (int icc = 0; icc < CIN; icc += 8) {
        __syncthreads();
        // input tile (zero padded)
        for (int idx = tid; idx < 8 * 324; idx += 256) {
            int ic = idx / 324;
            int rem = idx - ic * 324;
            int r = rem / 18;
            int cl = rem - r * 18;
            int gh = ty0 - 1 + r;
            int gw = tx0 - 1 + cl;
            float val = 0.f;
            if ((unsigned)gh < (unsigned)Hd && (unsigned)gw < (unsigned)Wd) {
                int gic = icc + ic;
                const float* src = (gic < cin1)
                    ? pin1 + ((size_t)b * cin1 + gic) * NPIX
                    : pin2 + ((size_t)b * cin2 + (gic - cin1)) * NPIX;
                val = src[gh * Wd + gw];
            }
            ti[ic][rem] = val;
        }
        // weights (coalesced float4): 72 rows x 64
        for (int idx = tid; idx < 72 * 16; idx += 256) {
            int r = idx >> 4;
            int c4 = (idx & 15) * 4;
            *(float4*)&tw[r][c4] = *(const float4*)&wt[(size_t)(icc * 9 + r) * OC + ocb + c4];
        }
        __syncthreads();

        for (int ic = 0; ic < 8; ic++) {
            float xv[4][6];
#pragma unroll
            for (int r = 0; r < 4; r++)
#pragma unroll
                for (int c = 0; c < 6; c++)
                    xv[r][c] = ti[ic][(py + r) * 18 + px + c];
#pragma unroll
            for (int dh = 0; dh < 3; dh++)
#pragma unroll
            for (int dw = 0; dw < 3; dw++) {
                float4 wA = *(const float4*)&tw[ic * 9 + dh * 3 + dw][ocg * 8];
                float4 wB = *(const float4*)&tw[ic * 9 + dh * 3 + dw][ocg * 8 + 4];
                float w8[8] = {wA.x, wA.y, wA.z, wA.w, wB.x, wB.y, wB.z, wB.w};
#pragma unroll
                for (int o = 0; o < 8; o++)
#pragma unroll
                    for (int r = 0; r < 2; r++)
#pragma unroll
                        for (int c = 0; c < 4; c++)
                            acc[o][r * 4 + c] += w8[o] * xv[r + dh][c + dw];
            }
        }
    }

#pragma unroll
    for (int o = 0; o < 8; o++) {
        int oc = ocb + ocg * 8 + o;
        float inv = bns[oc] * rsqrtf(bnv[oc] + 1e-5f);
        float add = bnb[oc] - bnm[oc] * inv;
#pragma unroll
        for (int r = 0; r < 2; r++) {
            float4 v;
            v.x = fmaxf(acc[o][r * 4 + 0] * inv + add, 0.f);
            v.y = fmaxf(acc[o][r * 4 + 1] * inv + add, 0.f);
            v.z = fmaxf(acc[o][r * 4 + 2] * inv + add, 0.f);
            v.w = fmaxf(acc[o][r * 4 + 3] * inv + add, 0.f);
            *(float4*)&out[((size_t)b * OC + oc) * NPIX + (ty0 + py + r) * Wd + tx0 + px] = v;
        }
    }
}

// ---------------- fused q/k/v 1x1 convs (from g_out1) ----------------
__global__ void __launch_bounds__(128) qkv_kernel(
    const float* __restrict__ wq, const float* __restrict__ bq,
    const float* __restrict__ wk, const float* __restrict__ bk,
    const float* __restrict__ wv, const float* __restrict__ bv)
{
    int b = blockIdx.y;
    int px0 = blockIdx.x * 64;
    int t = threadIdx.x;
    int px = t & 63;
    int half = t >> 6;

    __shared__ float xs[128][64];
    for (int idx = t; idx < 128 * 64; idx += 128) {
        int ic = idx >> 6;
        int p = idx & 63;
        xs[ic][p] = g_out1[((size_t)b * ICd + ic) * NPIX + px0 + p];
    }
    __syncthreads();

    for (int oc = half * 80; oc < half * 80 + 80; oc++) {
        const float* wrow;
        float bias;
        float* dst;
        if (oc < 16) {
            wrow = wq + oc * 128; bias = bq[oc];
            dst = g_q + ((size_t)b * QCd + oc) * NPIX;
        } else if (oc < 32) {
            int o = oc - 16;
            wrow = wk + o * 128; bias = bk[o];
            dst = g_k + ((size_t)b * QCd + o) * NPIX;
        } else {
            int o = oc - 32;
            wrow = wv + o * 128; bias = bv[o];
            dst = g_v + ((size_t)b * ICd + o) * NPIX;
        }
        float a = bias;
#pragma unroll 8
        for (int ic = 0; ic < 128; ic += 4) {
            float4 w4 = *(const float4*)(wrow + ic);
            a += w4.x * xs[ic][px] + w4.y * xs[ic + 1][px]
               + w4.z * xs[ic + 2][px] + w4.w * xs[ic + 3][px];
        }
        dst[px0 + px] = a;
    }
}

// ---------------- criss-cross attention: one block per (b,h) row ----------------
// dynamic smem: e[192][96], qs[16][96], ks[16][96], vr[2][96]
__global__ void __launch_bounds__(192) cca2_kernel(const float* __restrict__ gamma)
{
    extern __shared__ float sm[];
    float* e = sm;                   // 192*96
    float* qs = sm + 192 * 96;       // 16*96
    float* ks_ = qs + 16 * 96;       // 16*96
    float* vr = ks_ + 16 * 96;       // 2*96

    int h = blockIdx.x, b = blockIdx.y;
    int tid = threadIdx.x;
    const float* qb = g_q + (size_t)b * QCd * NPIX;
    const float* kb = g_k + (size_t)b * QCd * NPIX;
    const float* vb = g_v + (size_t)b * ICd * NPIX;

    for (int idx = tid; idx < 16 * 96; idx += 192) {
        int c = idx / 96, w = idx - c * 96;
        qs[c * 96 + w] = qb[c * NPIX + h * Wd + w];
        ks_[c * 96 + w] = kb[c * NPIX + h * Wd + w];
    }
    __syncthreads();

    // e_W rows 96..191: e[96+s][w] = sum_c q[c][w]*k[c][h][s]
    for (int idx = tid; idx < 96 * 96; idx += 192) {
        int s = idx / 96, w = idx - s * 96;
        float a = 0.f;
#pragma unroll
        for (int c = 0; c < 16; c++) a += qs[c * 96 + w] * ks_[c * 96 + s];
        e[(96 + s) * 96 + w] = a;
    }
    // e_H rows 0..95: e[s][w] = sum_c q[c][w]*k[c][s][w]  (diag -> -inf)
    for (int idx = tid; idx < 96 * 96; idx += 192) {
        int s = idx / 96, w = idx - s * 96;
        float a = 0.f;
#pragma unroll
        for (int c = 0; c < 16; c++) a += qs[c * 96 + w] * kb[c * NPIX + s * Wd + w];
        e[s * 96 + w] = (s == h) ? -1e30f : a;
    }
    __syncthreads();

    // softmax per column w over 192 entries
    if (tid < 96) {
        int w = tid;
        float M = -1e30f;
        for (int i = 0; i < 192; i++) M = fmaxf(M, e[i * 96 + w]);
        float S = 0.f;
        for (int i = 0; i < 192; i++) {
            float p = __expf(e[i * 96 + w] - M);
            e[i * 96 + w] = p;
            S += p;
        }
        float inv = 1.f / S;
        for (int i = 0; i < 192; i++) e[i * 96 + w] *= inv;
    }
    __syncthreads();

    // outputs: group g handles channels g*64..g*64+63
    int g = tid / 96;
    int w = tid - g * 96;
    float gam = __ldg(gamma);
    for (int cc = 0; cc < 64; cc++) {
        int c = g * 64 + cc;
        vr[g * 96 + w] = vb[(size_t)c * NPIX + h * Wd + w];
        __syncthreads();
        float oH = 0.f, oW = 0.f;
        const float* vcol = vb + (size_t)c * NPIX + w;
#pragma unroll 4
        for (int s = 0; s < 96; s++) {
            oH += vcol[s * Wd] * e[s * 96 + w];
            oW += vr[g * 96 + s] * e[(96 + s) * 96 + w];
        }
        size_t o = ((size_t)b * ICd + c) * NPIX + h * Wd + w;
        g_cca[o] = gam * (oH + oW) + g_out1[o];
        __syncthreads();
    }
}

// ---------------- CAM softmax over summed energy partials ----------------
__global__ void __launch_bounds__(128) cam_softmax_kernel()
{
    int b = blockIdx.y, c = blockIdx.x;
    int t = threadIdx.x;
    __shared__ float red[4];

    float4 v = make_float4(0.f, 0.f, 0.f, 0.f);
#pragma unroll
    for (int s = 0; s < KSPLIT; s++) {
        const float4 p = *(const float4*)&g_epart[(((size_t)(s * Bq + b)) * Cc + c) * Cc + t * 4];
        v.x += p.x; v.y += p.y; v.z += p.z; v.w += p.w;
    }
    float lmn = fminf(fminf(v.x, v.y), fminf(v.z, v.w));
#pragma unroll
    for (int o = 16; o; o >>= 1) lmn = fminf(lmn, __shfl_xor_sync(0xffffffffu, lmn, o));
    if ((t & 31) == 0) red[t >> 5] = lmn;
    __syncthreads();
    float mn = fminf(fminf(red[0], red[1]), fminf(red[2], red[3]));
    __syncthreads();

    float4 p;
    p.x = __expf(mn - v.x); p.y = __expf(mn - v.y);
    p.z = __expf(mn - v.z); p.w = __expf(mn - v.w);
    float ls = p.x + p.y + p.z + p.w;
#pragma unroll
    for (int o = 16; o; o >>= 1) ls += __shfl_xor_sync(0xffffffffu, ls, o);
    if ((t & 31) == 0) red[t >> 5] = ls;
    __syncthreads();
    float inv = 1.f / (red[0] + red[1] + red[2] + red[3]);
    p.x *= inv; p.y *= inv; p.z *= inv; p.w *= inv;
    *(float4*)&g_energy[((size_t)b * Cc + c) * Cc + t * 4] = p;
}

// ---------------- 128x128 fp32 GEMM, 8x8 per thread, reg-prefetch pipeline ----------------
// MODE 0 + NT: energy partials C[128x128] = A*B^T over k chunk
// MODE 1: C = A*B + bias[row]
// MODE 2: C = g_bott2 + gamma*(A*B) + addx
template<int MODE, bool NT>
__global__ void __launch_bounds__(256) sgemm128(
    const float* __restrict__ Aex, int A_id, size_t sA,
    const float* __restrict__ Bex, int B_id, size_t sB,
    float* __restrict__ Cex, int C_id, size_t sC,
    int M, int Nn, int K, int lda, int ldb,
    const float* __restrict__ bias,
    const float* __restrict__ addx,
    const float* __restrict__ gamma)
{
    int bz = blockIdx.z;
    int b, ks;
    if (NT) { b = bz / KSPLIT; ks = bz - b * KSPLIT; }
    else { b = bz; ks = 0; }

    const float* A = cbuf(A_id, Aex) + (size_t)b * sA;
    const float* Bm = cbuf(B_id, Bex) + (size_t)b * sB;
    float* Cm;
    if (NT) Cm = g_epart + (size_t)(ks * Bq + b) * Cc * Cc;
    else Cm = (C_id >= 0 ? wbuf(C_id) : Cex) + (size_t)b * sC;

    int k0s = NT ? ks * ECHUNK : 0;
    int k0e = NT ? k0s + ECHUNK : K;

    __shared__ float As[8][132];
    __shared__ float Bs[8][132];

    int tid = threadIdx.x;
    int tx = tid & 15, ty = tid >> 4;
    int row0 = blockIdx.y * 128, col0 = blockIdx.x * 128;

    int ar = tid >> 1, ak = (tid & 1) * 4;
    const float* Aptr = A + (size_t)(row0 + ar) * lda + ak;

    int br, bcol, bk;
    const float* Bptr;
    if (NT) { br = tid >> 1; bk = (tid & 1) * 4; bcol = 0;
              Bptr = Bm + (size_t)(col0 + br) * ldb + bk; }
    else    { br = tid >> 5; bcol = (tid & 31) * 4; bk = 0;
              Bptr = Bm + (size_t)br * ldb + col0 + bcol; }

    float acc[8][8];
#pragma unroll
    for (int i = 0; i < 8; i++)
#pragma unroll
        for (int j = 0; j < 8; j++) acc[i][j] = 0.f;

    float4 pa = *(const float4*)(Aptr + k0s);
    float4 pb = NT ? *(const float4*)(Bptr + k0s)
                   : *(const float4*)(Bptr + (size_t)k0s * ldb);

    for (int k0 = k0s; k0 < k0e; k0 += 8) {
        As[ak + 0][ar] = pa.x;
        As[ak + 1][ar] = pa.y;
        As[ak + 2][ar] = pa.z;
        As[ak + 3][ar] = pa.w;
        if (NT) {
            Bs[bk + 0][br] = pb.x;
            Bs[bk + 1][br] = pb.y;
            Bs[bk + 2][br] = pb.z;
            Bs[bk + 3][br] = pb.w;
        } else {
            *(float4*)&Bs[br][bcol] = pb;
        }
        __syncthreads();
        if (k0 + 8 < k0e) {
            pa = *(const float4*)(Aptr + k0 + 8);
            pb = NT ? *(const float4*)(Bptr + k0 + 8)
                    : *(const float4*)(Bptr + (size_t)(k0 + 8) * ldb);
        }
#pragma unroll
        for (int kk = 0; kk < 8; kk++) {
            float4 a0 = *(const float4*)&As[kk][ty * 8];
            float4 a1 = *(const float4*)&As[kk][ty * 8 + 4];
            float4 b0 = *(const float4*)&Bs[kk][tx * 8];
            float4 b1 = *(const float4*)&Bs[kk][tx * 8 + 4];
            float av[8] = {a0.x, a0.y, a0.z, a0.w, a1.x, a1.y, a1.z, a1.w};
            float bv[8] = {b0.x, b0.y, b0.z, b0.w, b1.x, b1.y, b1.z, b1.w};
#pragma unroll
            for (int i = 0; i < 8; i++)
#pragma unroll
                for (int j = 0; j < 8; j++)
                    acc[i][j] += av[i] * bv[j];
        }
        __syncthreads();
    }

    float g = (MODE == 2) ? __ldg(gamma) : 0.f;
#pragma unroll
    for (int i = 0; i < 8; i++) {
        int r = row0 + ty * 8 + i;
        size_t off = (size_t)r * Nn + col0 + tx * 8;
        if (MODE == 0) {
            *(float4*)&Cm[off] = make_float4(acc[i][0], acc[i][1], acc[i][2], acc[i][3]);
            *(float4*)&Cm[off + 4] = make_float4(acc[i][4], acc[i][5], acc[i][6], acc[i][7]);
        } else if (MODE == 1) {
            float bb = __ldg(&bias[r]);
            *(float4*)&Cm[off] = make_float4(acc[i][0] + bb, acc[i][1] + bb, acc[i][2] + bb, acc[i][3] + bb);
            *(float4*)&Cm[off + 4] = make_float4(acc[i][4] + bb, acc[i][5] + bb, acc[i][6] + bb, acc[i][7] + bb);
        } else {
            const float* bt = g_bott2 + (size_t)b * sC;
            const float* xx = addx + (size_t)b * sC;
            float4 t0 = *(const float4*)&bt[off];
            float4 t1 = *(const float4*)&bt[off + 4];
            float4 x0 = *(const float4*)&xx[off];
            float4 x1 = *(const float4*)&xx[off + 4];
            *(float4*)&Cm[off] = make_float4(t0.x + g * acc[i][0] + x0.x,
                                             t0.y + g * acc[i][1] + x0.y,
                                             t0.z + g * acc[i][2] + x0.z,
                                             t0.w + g * acc[i][3] + x0.w);
            *(float4*)&Cm[off + 4] = make_float4(t1.x + g * acc[i][4] + x1.x,
                                                 t1.y + g * acc[i][5] + x1.y,
                                                 t1.z + g * acc[i][6] + x1.z,
                                                 t1.w + g * acc[i][7] + x1.w);
        }
    }
}

// ---------------- launch ----------------
extern "C" void kernel_launch(void* const* d_in, const int* in_sizes, int n_in,
                              void* d_out, int out_size)
{
    const float* x        = (const float*)d_in[0];
    const float* conva_w  = (const float*)d_in[1];
    const float* bn1_s    = (const float*)d_in[2];
    const float* bn1_b    = (const float*)d_in[3];
    const float* bn1_m    = (const float*)d_in[4];
    const float* bn1_v    = (const float*)d_in[5];
    const float* wq       = (const float*)d_in[6];
    const float* bq       = (const float*)d_in[7];
    const float* wk       = (const float*)d_in[8];
    const float* bk       = (const float*)d_in[9];
    const float* wv       = (const float*)d_in[10];
    const float* bv       = (const float*)d_in[11];
    const float* gamma_cca= (const float*)d_in[12];
    const float* convb_w  = (const float*)d_in[13];
    const float* bn2_s    = (const float*)d_in[14];
    const float* bn2_b    = (const float*)d_in[15];
    const float* bn2_m    = (const float*)d_in[16];
    const float* bn2_v    = (const float*)d_in[17];
    const float* bot_w1   = (const float*)d_in[18];
    const float* bn3_s    = (const float*)d_in[19];
    const float* bn3_b    = (const float*)d_in[20];
    const float* bn3_m    = (const float*)d_in[21];
    const float* bn3_v    = (const float*)d_in[22];
    const float* bot_w2   = (const float*)d_in[23];
    const float* bot_b2   = (const float*)d_in[24];
    const float* gamma_cam= (const float*)d_in[25];
    float* out = (float*)d_out;

    const size_t sCN = (size_t)Cc * NPIX;
    const size_t sCC = (size_t)Cc * Cc;

    // weight transposes
    wtrans_kernel<<<256, 256>>>(conva_w, 9, Cc, ICd);
    wtrans_kernel<<<256, 256>>>(convb_w, 10, ICd, ICd);
    wtrans_kernel<<<256, 256>>>(bot_w1, 11, Cc + ICd, Cc);

    // 1) conva: 512 -> 128
    conv3x3_v2<<<dim3(36, ICd / 64, Bq), 256>>>(
        x, -1, Cc, -1, 0, 9, bn1_s, bn1_b, bn1_m, bn1_v, 0, ICd);

    // 2) q/k/v
    qkv_kernel<<<dim3(NPIX / 64, Bq), 128>>>(wq, bq, wk, bk, wv, bv);

    // 3) criss-cross attention
    int cca_smem = (192 * 96 + 16 * 96 * 2 + 2 * 96) * 4;
    cudaFuncSetAttribute(cca2_kernel, cudaFuncAttributeMaxDynamicSharedMemorySize, cca_smem);
    cca2_kernel<<<dim3(Hd, Bq), 192, cca_smem>>>(gamma_cca);

    // 4) convb: 128 -> 128 (input g_cca id 4)
    conv3x3_v2<<<dim3(36, ICd / 64, Bq), 256>>>(
        nullptr, 4, ICd, -1, 0, 10, bn2_s, bn2_b, bn2_m, bn2_v, 5, ICd);

    // 5) bot conv1 on concat(x, out2): 640 -> 512
    conv3x3_v2<<<dim3(36, Cc / 64, Bq), 256>>>(
        x, -1, Cc, 5, ICd, 11, bn3_s, bn3_b, bn3_m, bn3_v, 6, Cc);

    // 6) bot conv2 (1x1) + bias
    sgemm128<1, false><<<dim3(NPIX / 128, Cc / 128, Bq), 256>>>(
        bot_w2, -1, 0, nullptr, 6, sCN, nullptr, 7, sCN,
        Cc, NPIX, Cc, Cc, NPIX, bot_b2, nullptr, nullptr);

    // 7) CAM energy partials (split-K)
    sgemm128<0, true><<<dim3(Cc / 128, Cc / 128, Bq * KSPLIT), 256>>>(
        x, -1, sCN, x, -1, sCN, nullptr, -1, 0,
        Cc, Cc, NPIX, NPIX, NPIX, nullptr, nullptr, nullptr);

    // 8) CAM softmax (sums partials, writes attention to g_energy)
    cam_softmax_kernel<<<dim3(Cc, Bq), 128>>>();

    // 9) final: out = bott2 + gamma_cam * (att @ x) + x
    sgemm128<2, false><<<dim3(NPIX / 128, Cc / 128, Bq), 256>>>(
        nullptr, 8, sCC, x, -1, sCN, out, -1, sCN,
        Cc, NPIX, Cc, Cc, NPIX, nullptr, x, gamma_cam);
}

// round 3
// speedup vs baseline: 1.8273x; 1.0021x over previous
#include <cuda_runtime.h>

#define Bq 4
#define Cc 512
#define Hd 96
#define Wd 96
#define NPIX 9216
#define ICd 128
#define QCd 16
#define KSPLIT 6
#define ECHUNK 1536

// ---------------- scratch (static device allocations) ----------------
__device__ float g_out1[Bq * ICd * NPIX];
__device__ float g_q[Bq * QCd * NPIX];
__device__ float g_k[Bq * QCd * NPIX];
__device__ float g_v[Bq * ICd * NPIX];
__device__ float g_cca[Bq * ICd * NPIX];
__device__ float g_out2[Bq * ICd * NPIX];
__device__ float g_bott1[(size_t)Bq * Cc * NPIX];
__device__ float g_bott2[(size_t)Bq * Cc * NPIX];
__device__ float g_energy[Bq * Cc * Cc];
__device__ float g_wa[512 * 9 * 128];
__device__ float g_wb[128 * 9 * 128];
__device__ float g_w1[640 * 9 * 512];
__device__ float g_epart[(size_t)KSPLIT * Bq * Cc * Cc];

__device__ __forceinline__ float* wbuf(int id) {
    switch (id) {
        case 0: return g_out1;
        case 1: return g_q;
        case 2: return g_k;
        case 3: return g_v;
        case 4: return g_cca;
        case 5: return g_out2;
        case 6: return g_bott1;
        case 7: return g_bott2;
        case 8: return g_energy;
        case 9: return g_wa;
        case 10: return g_wb;
        case 11: return g_w1;
        case 12: return g_epart;
    }
    return nullptr;
}
__device__ __forceinline__ const float* cbuf(int id, const float* ext) {
    if (id < 0) return ext;
    return wbuf(id);
}

// ---------------- weight transpose: w[oc][ic][9] -> wt[(ic*9+tap)][oc] ----------------
__global__ void wtrans_kernel(const float* __restrict__ src, int dst_id, int CIN, int OC)
{
    float* dst = wbuf(dst_id);
    int n = OC * CIN * 9;
    for (int i = blockIdx.x * blockDim.x + threadIdx.x; i < n; i += gridDim.x * blockDim.x) {
        int oc = i / (CIN * 9);
        int rem = i - oc * (CIN * 9);   // ic*9+tap
        dst[rem * OC + oc] = src[i];
    }
}

// ---------------- conv3x3 + BN + ReLU, 64oc x 16x16 tile, 8oc x 8pix per thread ----------------
__global__ void __launch_bounds__(256) conv3x3_v2(
    const float* __restrict__ in1e, int in1_id, int cin1,
    int in2_id, int cin2,
    int wt_id,
    const float* __restrict__ bns, const float* __restrict__ bnb,
    const float* __restrict__ bnm, const float* __restrict__ bnv,
    int out_id, int OC)
{
    const float* pin1 = cbuf(in1_id, in1e);
    const float* pin2 = (in2_id >= 0) ? wbuf(in2_id) : nullptr;
    const float* wt = wbuf(wt_id);
    float* out = wbuf(out_id);
    const int CIN = cin1 + cin2;

    int tile = blockIdx.x;
    int tx0 = (tile % 6) * 16;
    int ty0 = (tile / 6) * 16;
    int ocb = blockIdx.y * 64;
    int b = blockIdx.z;
    int tid = threadIdx.x;
    int ocg = tid >> 5;
    int lane = tid & 31;
    int px = (lane & 3) * 4;
    int py = (lane >> 2) * 2;

    __shared__ float ti[8][324];     // 8 ic x 18x18
    __shared__ float tw[72][64];     // [(ic,tap)][oc]

    float acc[8][8];
#pragma unroll
    for (int o = 0; o < 8; o++)
#pragma unroll
        for (int p = 0; p < 8; p++) acc[o][p] = 0.f;

    for (int icc = 0; icc < CIN; icc += 8) {
        __syncthreads();
        // input tile (zero padded)
        for (int idx = tid; idx < 8 * 324; idx += 256) {
            int ic = idx / 324;
            int rem = idx - ic * 324;
            int r = rem / 18;
            int cl = rem - r * 18;
            int gh = ty0 - 1 + r;
            int gw = tx0 - 1 + cl;
            float val = 0.f;
            if ((unsigned)gh < (unsigned)Hd && (unsigned)gw < (unsigned)Wd) {
                int gic = icc + ic;
                const float* src = (gic < cin1)
                    ? pin1 + ((size_t)b * cin1 + gic) * NPIX
                    : pin2 + ((size_t)b * cin2 + (gic - cin1)) * NPIX;
                val = src[gh * Wd + gw];
            }
            ti[ic][rem] = val;
        }
        // weights (coalesced float4): 72 rows x 64
        for (int idx = tid; idx < 72 * 16; idx += 256) {
            int r = idx >> 4;
            int c4 = (idx & 15) * 4;
            *(float4*)&tw[r][c4] = *(const float4*)&wt[(size_t)(icc * 9 + r) * OC + ocb + c4];
        }
        __syncthreads();

        for (int ic = 0; ic < 8; ic++) {
            float xv[4][6];
#pragma unroll
            for (int r = 0; r < 4; r++)
#pragma unroll
                for (int c = 0; c < 6; c++)
                    xv[r][c] = ti[ic][(py + r) * 18 + px + c];
#pragma unroll
            for (int dh = 0; dh < 3; dh++)
#pragma unroll
            for (int dw = 0; dw < 3; dw++) {
                float4 wA = *(const float4*)&tw[ic * 9 + dh * 3 + dw][ocg * 8];
                float4 wB = *(const float4*)&tw[ic * 9 + dh * 3 + dw][ocg * 8 + 4];
                float w8[8] = {wA.x, wA.y, wA.z, wA.w, wB.x, wB.y, wB.z, wB.w};
#pragma unroll
                for (int o = 0; o < 8; o++)
#pragma unroll
                    for (int r = 0; r < 2; r++)
#pragma unroll
                        for (int c = 0; c < 4; c++)
                            acc[o][r * 4 + c] += w8[o] * xv[r + dh][c + dw];
            }
        }
    }

#pragma unroll
    for (int o = 0; o < 8; o++) {
        int oc = ocb + ocg * 8 + o;
        float inv = bns[oc] * rsqrtf(bnv[oc] + 1e-5f);
        float add = bnb[oc] - bnm[oc] * inv;
#pragma unroll
        for (int r = 0; r < 2; r++) {
            float4 v;
            v.x = fmaxf(acc[o][r * 4 + 0] * inv + add, 0.f);
            v.y = fmaxf(acc[o][r * 4 + 1] * inv + add, 0.f);
            v.z = fmaxf(acc[o][r * 4 + 2] * inv + add, 0.f);
            v.w = fmaxf(acc[o][r * 4 + 3] * inv + add, 0.f);
            *(float4*)&out[((size_t)b * OC + oc) * NPIX + (ty0 + py + r) * Wd + tx0 + px] = v;
        }
    }
}

// ---------------- fused q/k/v 1x1 convs (from g_out1) ----------------
__global__ void __launch_bounds__(128) qkv_kernel(
    const float* __restrict__ wq, const float* __restrict__ bq,
    const float* __restrict__ wk, const float* __restrict__ bk,
    const float* __restrict__ wv, const float* __restrict__ bv)
{
    int b = blockIdx.y;
    int px0 = blockIdx.x * 64;
    int t = threadIdx.x;
    int px = t & 63;
    int half = t >> 6;

    __shared__ float xs[128][64];
    for (int idx = t; idx < 128 * 64; idx += 128) {
        int ic = idx >> 6;
        int p = idx & 63;
        xs[ic][p] = g_out1[((size_t)b * ICd + ic) * NPIX + px0 + p];
    }
    __syncthreads();

    for (int oc = half * 80; oc < half * 80 + 80; oc++) {
        const float* wrow;
        float bias;
        float* dst;
        if (oc < 16) {
            wrow = wq + oc * 128; bias = bq[oc];
            dst = g_q + ((size_t)b * QCd + oc) * NPIX;
        } else if (oc < 32) {
            int o = oc - 16;
            wrow = wk + o * 128; bias = bk[o];
            dst = g_k + ((size_t)b * QCd + o) * NPIX;
        } else {
            int o = oc - 32;
            wrow = wv + o * 128; bias = bv[o];
            dst = g_v + ((size_t)b * ICd + o) * NPIX;
        }
        float a = bias;
#pragma unroll 8
        for (int ic = 0; ic < 128; ic += 4) {
            float4 w4 = *(const float4*)(wrow + ic);
            a += w4.x * xs[ic][px] + w4.y * xs[ic + 1][px]
               + w4.z * xs[ic + 2][px] + w4.w * xs[ic + 3][px];
        }
        dst[px0 + px] = a;
    }
}

// ---------------- criss-cross attention: one block per (b,h) row ----------------
// dynamic smem: e[192][96], qs[16][96], ks[16][96], vr[2][96]
__global__ void __launch_bounds__(192) cca2_kernel(const float* __restrict__ gamma)
{
    extern __shared__ float sm[];
    float* e = sm;                   // 192*96
    float* qs = sm + 192 * 96;       // 16*96
    float* ks_ = qs + 16 * 96;       // 16*96
    float* vr = ks_ + 16 * 96;       // 2*96

    int h = blockIdx.x, b = blockIdx.y;
    int tid = threadIdx.x;
    const float* qb = g_q + (size_t)b * QCd * NPIX;
    const float* kb = g_k + (size_t)b * QCd * NPIX;
    const float* vb = g_v + (size_t)b * ICd * NPIX;

    for (int idx = tid; idx < 16 * 96; idx += 192) {
        int c = idx / 96, w = idx - c * 96;
        qs[c * 96 + w] = qb[c * NPIX + h * Wd + w];
        ks_[c * 96 + w] = kb[c * NPIX + h * Wd + w];
    }
    __syncthreads();

    // e_W rows 96..191: e[96+s][w] = sum_c q[c][w]*k[c][h][s]
    for (int idx = tid; idx < 96 * 96; idx += 192) {
        int s = idx / 96, w = idx - s * 96;
        float a = 0.f;
#pragma unroll
        for (int c = 0; c < 16; c++) a += qs[c * 96 + w] * ks_[c * 96 + s];
        e[(96 + s) * 96 + w] = a;
    }
    // e_H rows 0..95: e[s][w] = sum_c q[c][w]*k[c][s][w]  (diag -> -inf)
    for (int idx = tid; idx < 96 * 96; idx += 192) {
        int s = idx / 96, w = idx - s * 96;
        float a = 0.f;
#pragma unroll
        for (int c = 0; c < 16; c++) a += qs[c * 96 + w] * kb[c * NPIX + s * Wd + w];
        e[s * 96 + w] = (s == h) ? -1e30f : a;
    }
    __syncthreads();

    // softmax per column w over 192 entries
    if (tid < 96) {
        int w = tid;
        float M = -1e30f;
        for (int i = 0; i < 192; i++) M = fmaxf(M, e[i * 96 + w]);
        float S = 0.f;
        for (int i = 0; i < 192; i++) {
            float p = __expf(e[i * 96 + w] - M);
            e[i * 96 + w] = p;
            S += p;
        }
        float inv = 1.f / S;
        for (int i = 0; i < 192; i++) e[i * 96 + w] *= inv;
    }
    __syncthreads();

    // outputs: group g handles channels g*64..g*64+63
    int g = tid / 96;
    int w = tid - g * 96;
    float gam = __ldg(gamma);
    for (int cc = 0; cc < 64; cc++) {
        int c = g * 64 + cc;
        vr[g * 96 + w] = vb[(size_t)c * NPIX + h * Wd + w];
        __syncthreads();
        float oH = 0.f, oW = 0.f;
        const float* vcol = vb + (size_t)c * NPIX + w;
#pragma unroll 4
        for (int s = 0; s < 96; s++) {
            oH += vcol[s * Wd] * e[s * 96 + w];
            oW += vr[g * 96 + s] * e[(96 + s) * 96 + w];
        }
        size_t o = ((size_t)b * ICd + c) * NPIX + h * Wd + w;
        g_cca[o] = gam * (oH + oW) + g_out1[o];
        __syncthreads();
    }
}

// ---------------- CAM softmax over summed energy partials ----------------
__global__ void __launch_bounds__(128) cam_softmax_kernel()
{
    int b = blockIdx.y, c = blockIdx.x;
    int t = threadIdx.x;
    __shared__ float red[4];

    float4 v = make_float4(0.f, 0.f, 0.f, 0.f);
#pragma unroll
    for (int s = 0; s < KSPLIT; s++) {
        const float4 p = *(const float4*)&g_epart[(((size_t)(s * Bq + b)) * Cc + c) * Cc + t * 4];
        v.x += p.x; v.y += p.y; v.z += p.z; v.w += p.w;
    }
    float lmn = fminf(fminf(v.x, v.y), fminf(v.z, v.w));
#pragma unroll
    for (int o = 16; o; o >>= 1) lmn = fminf(lmn, __shfl_xor_sync(0xffffffffu, lmn, o));
    if ((t & 31) == 0) red[t >> 5] = lmn;
    __syncthreads();
    float mn = fminf(fminf(red[0], red[1]), fminf(red[2], red[3]));
    __syncthreads();

    float4 p;
    p.x = __expf(mn - v.x); p.y = __expf(mn - v.y);
    p.z = __expf(mn - v.z); p.w = __expf(mn - v.w);
    float ls = p.x + p.y + p.z + p.w;
#pragma unroll
    for (int o = 16; o; o >>= 1) ls += __shfl_xor_sync(0xffffffffu, ls, o);
    if ((t & 31) == 0) red[t >> 5] = ls;
    __syncthreads();
    float inv = 1.f / (red[0] + red[1] + red[2] + red[3]);
    p.x *= inv; p.y *= inv; p.z *= inv; p.w *= inv;
    *(float4*)&g_energy[((size_t)b * Cc + c) * Cc + t * 4] = p;
}

// ---------------- 128x128 fp32 GEMM, 8x8 per thread, reg-prefetch pipeline ----------------
// MODE 0 + NT: energy partials C[128x128] = A*B^T over k chunk
// MODE 1: C = A*B + bias[row]
// MODE 2: C = g_bott2 + gamma*(A*B) + addx
template<int MODE, bool NT>
__global__ void __launch_bounds__(256) sgemm128(
    const float* __restrict__ Aex, int A_id, size_t sA,
    const float* __restrict__ Bex, int B_id, size_t sB,
    float* __restrict__ Cex, int C_id, size_t sC,
    int M, int Nn, int K, int lda, int ldb,
    const float* __restrict__ bias,
    const float* __restrict__ addx,
    const float* __restrict__ gamma)
{
    int bz = blockIdx.z;
    int b, ks;
    if (NT) { b = bz / KSPLIT; ks = bz - b * KSPLIT; }
    else { b = bz; ks = 0; }

    const float* A = cbuf(A_id, Aex) + (size_t)b * sA;
    const float* Bm = cbuf(B_id, Bex) + (size_t)b * sB;
    float* Cm;
    if (NT) Cm = g_epart + (size_t)(ks * Bq + b) * Cc * Cc;
    else Cm = (C_id >= 0 ? wbuf(C_id) : Cex) + (size_t)b * sC;

    int k0s = NT ? ks * ECHUNK : 0;
    int k0e = NT ? k0s + ECHUNK : K;

    __shared__ float As[8][132];
    __shared__ float Bs[8][132];

    int tid = threadIdx.x;
    int tx = tid & 15, ty = tid >> 4;
    int row0 = blockIdx.y * 128, col0 = blockIdx.x * 128;

    int ar = tid >> 1, ak = (tid & 1) * 4;
    const float* Aptr = A + (size_t)(row0 + ar) * lda + ak;

    int br, bcol, bk;
    const float* Bptr;
    if (NT) { br = tid >> 1; bk = (tid & 1) * 4; bcol = 0;
              Bptr = Bm + (size_t)(col0 + br) * ldb + bk; }
    else    { br = tid >> 5; bcol = (tid & 31) * 4; bk = 0;
              Bptr = Bm + (size_t)br * ldb + col0 + bcol; }

    float acc[8][8];
#pragma unroll
    for (int i = 0; i < 8; i++)
#pragma unroll
        for (int j = 0; j < 8; j++) acc[i][j] = 0.f;

    float4 pa = *(const float4*)(Aptr + k0s);
    float4 pb = NT ? *(const float4*)(Bptr + k0s)
                   : *(const float4*)(Bptr + (size_t)k0s * ldb);

    for (int k0 = k0s; k0 < k0e; k0 += 8) {
        As[ak + 0][ar] = pa.x;
        As[ak + 1][ar] = pa.y;
        As[ak + 2][ar] = pa.z;
        As[ak + 3][ar] = pa.w;
        if (NT) {
            Bs[bk + 0][br] = pb.x;
            Bs[bk + 1][br] = pb.y;
            Bs[bk + 2][br] = pb.z;
            Bs[bk + 3][br] = pb.w;
        } else {
            *(float4*)&Bs[br][bcol] = pb;
        }
        __syncthreads();
        if (k0 + 8 < k0e) {
            pa = *(const float4*)(Aptr + k0 + 8);
            pb = NT ? *(const float4*)(Bptr + k0 + 8)
                    : *(const float4*)(Bptr + (size_t)(k0 + 8) * ldb);
        }
#pragma unroll
        for (int kk = 0; kk < 8; kk++) {
            float4 a0 = *(const float4*)&As[kk][ty * 8];
            float4 a1 = *(const float4*)&As[kk][ty * 8 + 4];
            float4 b0 = *(const float4*)&Bs[kk][tx * 8];
            float4 b1 = *(const float4*)&Bs[kk][tx * 8 + 4];
            float av[8] = {a0.x, a0.y, a0.z, a0.w, a1.x, a1.y, a1.z, a1.w};
            float bv[8] = {b0.x, b0.y, b0.z, b0.w, b1.x, b1.y, b1.z, b1.w};
#pragma unroll
            for (int i = 0; i < 8; i++)
#pragma unroll
                for (int j = 0; j < 8; j++)
                    acc[i][j] += av[i] * bv[j];
        }
        __syncthreads();
    }

    float g = (MODE == 2) ? __ldg(gamma) : 0.f;
#pragma unroll
    for (int i = 0; i < 8; i++) {
        int r = row0 + ty * 8 + i;
        size_t off = (size_t)r * Nn + col0 + tx * 8;
        if (MODE == 0) {
            *(float4*)&Cm[off] = make_float4(acc[i][0], acc[i][1], acc[i][2], acc[i][3]);
            *(float4*)&Cm[off + 4] = make_float4(acc[i][4], acc[i][5], acc[i][6], acc[i][7]);
        } else if (MODE == 1) {
            float bb = __ldg(&bias[r]);
            *(float4*)&Cm[off] = make_float4(acc[i][0] + bb, acc[i][1] + bb, acc[i][2] + bb, acc[i][3] + bb);
            *(float4*)&Cm[off + 4] = make_float4(acc[i][4] + bb, acc[i][5] + bb, acc[i][6] + bb, acc[i][7] + bb);
        } else {
            const float* bt = g_bott2 + (size_t)b * sC;
            const float* xx = addx + (size_t)b * sC;
            float4 t0 = *(const float4*)&bt[off];
            float4 t1 = *(const float4*)&bt[off + 4];
            float4 x0 = *(const float4*)&xx[off];
            float4 x1 = *(const float4*)&xx[off + 4];
            *(float4*)&Cm[off] = make_float4(t0.x + g * acc[i][0] + x0.x,
                                             t0.y + g * acc[i][1] + x0.y,
                                             t0.z + g * acc[i][2] + x0.z,
                                             t0.w + g * acc[i][3] + x0.w);
            *(float4*)&Cm[off + 4] = make_float4(t1.x + g * acc[i][4] + x1.x,
                                                 t1.y + g * acc[i][5] + x1.y,
                                                 t1.z + g * acc[i][6] + x1.z,
                                                 t1.w + g * acc[i][7] + x1.w);
        }
    }
}

// ---------------- launch ----------------
extern "C" void kernel_launch(void* const* d_in, const int* in_sizes, int n_in,
                              void* d_out, int out_size)
{
    const float* x        = (const float*)d_in[0];
    const float* conva_w  = (const float*)d_in[1];
    const float* bn1_s    = (const float*)d_in[2];
    const float* bn1_b    = (const float*)d_in[3];
    const float* bn1_m    = (const float*)d_in[4];
    const float* bn1_v    = (const float*)d_in[5];
    const float* wq       = (const float*)d_in[6];
    const float* bq       = (const float*)d_in[7];
    const float* wk       = (const float*)d_in[8];
    const float* bk       = (const float*)d_in[9];
    const float* wv       = (const float*)d_in[10];
    const float* bv       = (const float*)d_in[11];
    const float* gamma_cca= (const float*)d_in[12];
    const float* convb_w  = (const float*)d_in[13];
    const float* bn2_s    = (const float*)d_in[14];
    const float* bn2_b    = (const float*)d_in[15];
    const float* bn2_m    = (const float*)d_in[16];
    const float* bn2_v    = (const float*)d_in[17];
    const float* bot_w1   = (const float*)d_in[18];
    const float* bn3_s    = (const float*)d_in[19];
    const float* bn3_b    = (const float*)d_in[20];
    const float* bn3_m    = (const float*)d_in[21];
    const float* bn3_v    = (const float*)d_in[22];
    const float* bot_w2   = (const float*)d_in[23];
    const float* bot_b2   = (const float*)d_in[24];
    const float* gamma_cam= (const float*)d_in[25];
    float* out = (float*)d_out;

    const size_t sCN = (size_t)Cc * NPIX;
    const size_t sCC = (size_t)Cc * Cc;

    // weight transposes
    wtrans_kernel<<<256, 256>>>(conva_w, 9, Cc, ICd);
    wtrans_kernel<<<256, 256>>>(convb_w, 10, ICd, ICd);
    wtrans_kernel<<<256, 256>>>(bot_w1, 11, Cc + ICd, Cc);

    // 1) conva: 512 -> 128
    conv3x3_v2<<<dim3(36, ICd / 64, Bq), 256>>>(
        x, -1, Cc, -1, 0, 9, bn1_s, bn1_b, bn1_m, bn1_v, 0, ICd);

    // 2) q/k/v
    qkv_kernel<<<dim3(NPIX / 64, Bq), 128>>>(wq, bq, wk, bk, wv, bv);

    // 3) criss-cross attention
    int cca_smem = (192 * 96 + 16 * 96 * 2 + 2 * 96) * 4;
    cudaFuncSetAttribute(cca2_kernel, cudaFuncAttributeMaxDynamicSharedMemorySize, cca_smem);
    cca2_kernel<<<dim3(Hd, Bq), 192, cca_smem>>>(gamma_cca);

    // 4) convb: 128 -> 128 (input g_cca id 4)
    conv3x3_v2<<<dim3(36, ICd / 64, Bq), 256>>>(
        nullptr, 4, ICd, -1, 0, 10, bn2_s, bn2_b, bn2_m, bn2_v, 5, ICd);

    // 5) bot conv1 on concat(x, out2): 640 -> 512
    conv3x3_v2<<<dim3(36, Cc / 64, Bq), 256>>>(
        x, -1, Cc, 5, ICd, 11, bn3_s, bn3_b, bn3_m, bn3_v, 6, Cc);

    // 6) bot conv2 (1x1) + bias
    sgemm128<1, false><<<dim3(NPIX / 128, Cc / 128, Bq), 256>>>(
        bot_w2, -1, 0, nullptr, 6, sCN, nullptr, 7, sCN,
        Cc, NPIX, Cc, Cc, NPIX, bot_b2, nullptr, nullptr);

    // 7) CAM energy partials (split-K)
    sgemm128<0, true><<<dim3(Cc / 128, Cc / 128, Bq * KSPLIT), 256>>>(
        x, -1, sCN, x, -1, sCN, nullptr, -1, 0,
        Cc, Cc, NPIX, NPIX, NPIX, nullptr, nullptr, nullptr);

    // 8) CAM softmax (sums partials, writes attention to g_energy)
    cam_softmax_kernel<<<dim3(Cc, Bq), 128>>>();

    // 9) final: out = bott2 + gamma_cam * (att @ x) + x
    sgemm128<2, false><<<dim3(NPIX / 128, Cc / 128, Bq), 256>>>(
        nullptr, 8, sCC, x, -1, sCN, out, -1, sCN,
        Cc, NPIX, Cc, Cc, NPIX, nullptr, x, gamma_cam);
}

// round 5
// speedup vs baseline: 3.3662x; 1.8422x over previous
#include <cuda_runtime.h>
#include <cstdint>

#define Bq 4
#define Cc 512
#define NPIX 9216
#define ICd 128
#define QCd 16
#define Hd 96
#define Wd 96
#define KSPLIT 6
#define ECHUNK 1536

// ---------------- scratch ----------------
__device__ float g_xr[(size_t)Bq * Cc * NPIX];
__device__ float g_out1[Bq * ICd * NPIX];
__device__ float g_q[Bq * QCd * NPIX];
__device__ float g_k[Bq * QCd * NPIX];
__device__ float g_v[Bq * ICd * NPIX];
__device__ float g_cca[Bq * ICd * NPIX];
__device__ float g_out2[Bq * ICd * NPIX];
__device__ float g_bott1[(size_t)Bq * Cc * NPIX];
__device__ float g_bott2[(size_t)Bq * Cc * NPIX];
__device__ float g_energy[Bq * Cc * Cc];
__device__ float g_epart[(size_t)KSPLIT * Bq * Cc * Cc];
__device__ float g_wta[9 * 128 * 512];
__device__ float g_wtb[9 * 128 * 128];
__device__ float g_wt1[9 * 512 * 640];
__device__ float g_w2r[512 * 512];

__device__ __forceinline__ float tf32r(float x) {
    uint32_t u;
    asm("cvt.rna.tf32.f32 %0, %1;" : "=r"(u) : "f"(x));
    return __uint_as_float(u);
}

__device__ __forceinline__ void mma1688(float* c, const uint32_t* a, const uint32_t* b) {
    asm volatile(
        "mma.sync.aligned.m16n8k8.row.col.f32.tf32.tf32.f32 "
        "{%0,%1,%2,%3}, {%4,%5,%6,%7}, {%8,%9}, {%0,%1,%2,%3};"
        : "+f"(c[0]), "+f"(c[1]), "+f"(c[2]), "+f"(c[3])
        : "r"(a[0]), "r"(a[1]), "r"(a[2]), "r"(a[3]), "r"(b[0]), "r"(b[1]));
}

// ---------------- prep ----------------
__global__ void roundcopy4(const float* __restrict__ s, float* __restrict__ d, int n4) {
    for (int i = blockIdx.x * blockDim.x + threadIdx.x; i < n4; i += gridDim.x * blockDim.x) {
        float4 v = ((const float4*)s)[i];
        v.x = tf32r(v.x); v.y = tf32r(v.y); v.z = tf32r(v.z); v.w = tf32r(v.w);
        ((float4*)d)[i] = v;
    }
}
__global__ void wtrans_tf32(const float* __restrict__ src, float* __restrict__ dst,
                            int CIN, int OC) {
    int n = OC * CIN * 9;
    for (int i = blockIdx.x * blockDim.x + threadIdx.x; i < n; i += gridDim.x * blockDim.x) {
        int oc = i / (CIN * 9);
        int rem = i - oc * (CIN * 9);
        int ic = rem / 9;
        int tap = rem - ic * 9;
        dst[((size_t)tap * OC + oc) * CIN + ic] = tf32r(src[i]);
    }
}

// ---------------- tf32 tensor-core implicit-GEMM conv / gemm ----------------
// C[oc][px] = sum_k A[oc][k] * B[k][px];  k = tap*CIN + ic.
// CTA: 128 oc x 128 px, BK=16. 8 warps, each 64x32 via m16n8k8.
#define M_BNRELU 0
#define M_BIAS   1
#define M_FINAL  2

template<int NTAPS, int MODE, bool ROUND>
__global__ void __launch_bounds__(256, 2) conv_tc(
    const float* __restrict__ in1, int cin1,
    const float* __restrict__ in2, int cin2,
    const float* __restrict__ Aw, size_t Astride, int OCtot,
    float* __restrict__ outp,
    const float* __restrict__ q0, const float* __restrict__ q1,
    const float* __restrict__ q2, const float* __restrict__ q3,
    const float* __restrict__ fadd1, const float* __restrict__ fadd2,
    const float* __restrict__ gma)
{
    const int CIN = cin1 + cin2;
    const int NCHUNK = (NTAPS * CIN) / 16;

    __shared__ float As[2][128][20];
    __shared__ float Bs[2][16][132];

    int tid = threadIdx.x, lane = tid & 31, wid = tid >> 5;
    int wm = (wid & 1) * 64, wn = (wid >> 1) * 32;
    int px0 = blockIdx.x * 128;
    int oc0 = blockIdx.y * 128;
    int b = blockIdx.z;
    in1 += (size_t)b * cin1 * NPIX;
    if (cin2 > 0) in2 += (size_t)b * cin2 * NPIX;
    outp += (size_t)b * OCtot * NPIX;
    const float* Ab = Aw + Astride * b;

    int arow = tid >> 1, akq = (tid & 1) * 8;

    float4 pa0, pa1;
    float pb[8];

    auto loadA = [&](int c) {
        int ko = c * 16;
        int tap = (NTAPS == 9) ? ko / CIN : 0;
        int ic = ko - tap * CIN;
        const float* ap = Ab + ((size_t)tap * OCtot + oc0 + arow) * CIN + ic + akq;
        pa0 = *(const float4*)ap;
        pa1 = *(const float4*)(ap + 4);
    };
    auto loadB = [&](int c) {
        int ko = c * 16;
        int tap = (NTAPS == 9) ? ko / CIN : 0;
        int ic = ko - tap * CIN;
        int dh = (NTAPS == 9) ? tap / 3 - 1 : 0;
        int dw = (NTAPS == 9) ? tap % 3 - 1 : 0;
#pragma unroll
        for (int l = 0; l < 8; l++) {
            int idx = tid + l * 256;
            int k = idx >> 7, j = idx & 127;
            int px = px0 + j;
            int ch = ic + k;
            const float* src = (ch < cin1) ? (in1 + (size_t)ch * NPIX)
                                           : (in2 + (size_t)(ch - cin1) * NPIX);
            float v;
            if (NTAPS == 9) {
                int h = px / 96, w = px - h * 96;
                int hh = h + dh, ww = w + dw;
                bool ok = ((unsigned)hh < 96u) && ((unsigned)ww < 96u);
                v = ok ? __ldg(src + px + dh * 96 + dw) : 0.f;
            } else {
                v = __ldg(src + px);
            }
            pb[l] = v;
        }
    };
    auto storeAB = [&](int s) {
        *(float4*)&As[s][arow][akq] = pa0;
        *(float4*)&As[s][arow][akq + 4] = pa1;
#pragma unroll
        for (int l = 0; l < 8; l++) {
            int idx = tid + l * 256;
            Bs[s][idx >> 7][idx & 127] = pb[l];
        }
    };

    float acc[4][4][4];
#pragma unroll
    for (int i = 0; i < 4; i++)
#pragma unroll
        for (int j = 0; j < 4; j++)
#pragma unroll
            for (int r = 0; r < 4; r++) acc[i][j][r] = 0.f;

    loadA(0); loadB(0);
    storeAB(0);
    __syncthreads();

    for (int c = 0; c < NCHUNK; c++) {
        int s = c & 1;
        if (c + 1 < NCHUNK) { loadA(c + 1); loadB(c + 1); }
#pragma unroll
        for (int kk = 0; kk < 16; kk += 8) {
            uint32_t af[4][4], bf[4][2];
            int kq = kk + (lane & 3);
            int g4 = lane >> 2;
#pragma unroll
            for (int i = 0; i < 4; i++) {
                int m = wm + i * 16 + g4;
                af[i][0] = __float_as_uint(As[s][m][kq]);
                af[i][1] = __float_as_uint(As[s][m + 8][kq]);
                af[i][2] = __float_as_uint(As[s][m][kq + 4]);
                af[i][3] = __float_as_uint(As[s][m + 8][kq + 4]);
            }
#pragma unroll
            for (int j = 0; j < 4; j++) {
                int n = wn + j * 8 + g4;
                bf[j][0] = __float_as_uint(Bs[s][kq][n]);
                bf[j][1] = __float_as_uint(Bs[s][kq + 4][n]);
            }
#pragma unroll
            for (int i = 0; i < 4; i++)
#pragma unroll
                for (int j = 0; j < 4; j++)
                    mma1688(acc[i][j], af[i], bf[j]);
        }
        __syncthreads();
        if (c + 1 < NCHUNK) {
            storeAB((c + 1) & 1);
            __syncthreads();
        }
    }

    // epilogue: c0,c1 at (row, col..col+1); c2,c3 at (row+8, ...)
    float gv = (MODE == M_FINAL) ? __ldg(gma) : 0.f;
    const float* bt = (MODE == M_FINAL) ? (fadd1 + (size_t)b * Cc * NPIX) : nullptr;
    const float* xx = (MODE == M_FINAL) ? (fadd2 + (size_t)b * Cc * NPIX) : nullptr;
#pragma unroll
    for (int i = 0; i < 4; i++) {
#pragma unroll
        for (int hh = 0; hh < 2; hh++) {
            int row = oc0 + wm + i * 16 + (lane >> 2) + hh * 8;
            float inv = 0.f, add = 0.f;
            if (MODE == M_BNRELU) {
                inv = __ldg(q0 + row) * rsqrtf(__ldg(q3 + row) + 1e-5f);
                add = __ldg(q1 + row) - __ldg(q2 + row) * inv;
            } else if (MODE == M_BIAS) {
                add = __ldg(q0 + row);
            }
#pragma unroll
            for (int j = 0; j < 4; j++) {
                int col = px0 + wn + j * 8 + (lane & 3) * 2;
                size_t off = (size_t)row * NPIX + col;
                float v0 = acc[i][j][hh * 2 + 0];
                float v1 = acc[i][j][hh * 2 + 1];
                if (MODE == M_BNRELU) {
                    v0 = fmaxf(v0 * inv + add, 0.f);
                    v1 = fmaxf(v1 * inv + add, 0.f);
                } else if (MODE == M_BIAS) {
                    v0 += add; v1 += add;
                } else {
                    float2 t = *(const float2*)(bt + off);
                    float2 xv = *(const float2*)(xx + off);
                    v0 = t.x + gv * v0 + xv.x;
                    v1 = t.y + gv * v1 + xv.y;
                }
                if (ROUND) { v0 = tf32r(v0); v1 = tf32r(v1); }
                *(float2*)(outp + off) = make_float2(v0, v1);
            }
        }
    }
}

// ---------------- q/k/v 1x1 convs ----------------
__global__ void __launch_bounds__(128) qkv_kernel(
    const float* __restrict__ wq, const float* __restrict__ bq,
    const float* __restrict__ wk, const float* __restrict__ bk,
    const float* __restrict__ wv, const float* __restrict__ bv)
{
    int b = blockIdx.y;
    int px0 = blockIdx.x * 64;
    int t = threadIdx.x;
    int px = t & 63;
    int half = t >> 6;
    __shared__ float xs[128][64];
    for (int idx = t; idx < 128 * 64; idx += 128) {
        int ic = idx >> 6, p = idx & 63;
        xs[ic][p] = g_out1[((size_t)b * ICd + ic) * NPIX + px0 + p];
    }
    __syncthreads();
    for (int oc = half * 80; oc < half * 80 + 80; oc++) {
        const float* wrow; float bias; float* dst;
        if (oc < 16) { wrow = wq + oc * 128; bias = bq[oc];
                       dst = g_q + ((size_t)b * QCd + oc) * NPIX; }
        else if (oc < 32) { int o = oc - 16; wrow = wk + o * 128; bias = bk[o];
                            dst = g_k + ((size_t)b * QCd + o) * NPIX; }
        else { int o = oc - 32; wrow = wv + o * 128; bias = bv[o];
               dst = g_v + ((size_t)b * ICd + o) * NPIX; }
        float a = bias;
#pragma unroll 8
        for (int ic = 0; ic < 128; ic += 4) {
            float4 w4 = *(const float4*)(wrow + ic);
            a += w4.x * xs[ic][px] + w4.y * xs[ic + 1][px]
               + w4.z * xs[ic + 2][px] + w4.w * xs[ic + 3][px];
        }
        dst[px0 + px] = a;
    }
}

// ---------------- criss-cross attention ----------------
__global__ void __launch_bounds__(192) cca2_kernel(const float* __restrict__ gamma)
{
    extern __shared__ float sm[];
    float* e = sm;
    float* qs = sm + 192 * 96;
    float* ks_ = qs + 16 * 96;
    float* vr = ks_ + 16 * 96;

    int h = blockIdx.x, b = blockIdx.y;
    int tid = threadIdx.x;
    const float* qb = g_q + (size_t)b * QCd * NPIX;
    const float* kb = g_k + (size_t)b * QCd * NPIX;
    const float* vb = g_v + (size_t)b * ICd * NPIX;

    for (int idx = tid; idx < 16 * 96; idx += 192) {
        int c = idx / 96, w = idx - c * 96;
        qs[c * 96 + w] = qb[c * NPIX + h * Wd + w];
        ks_[c * 96 + w] = kb[c * NPIX + h * Wd + w];
    }
    __syncthreads();
    for (int idx = tid; idx < 96 * 96; idx += 192) {
        int s = idx / 96, w = idx - s * 96;
        float a = 0.f;
#pragma unroll
        for (int c = 0; c < 16; c++) a += qs[c * 96 + w] * ks_[c * 96 + s];
        e[(96 + s) * 96 + w] = a;
    }
    for (int idx = tid; idx < 96 * 96; idx += 192) {
        int s = idx / 96, w = idx - s * 96;
        float a = 0.f;
#pragma unroll
        for (int c = 0; c < 16; c++) a += qs[c * 96 + w] * kb[c * NPIX + s * Wd + w];
        e[s * 96 + w] = (s == h) ? -1e30f : a;
    }
    __syncthreads();
    if (tid < 96) {
        int w = tid;
        float M = -1e30f;
        for (int i = 0; i < 192; i++) M = fmaxf(M, e[i * 96 + w]);
        float S = 0.f;
        for (int i = 0; i < 192; i++) {
            float p = __expf(e[i * 96 + w] - M);
            e[i * 96 + w] = p; S += p;
        }
        float inv = 1.f / S;
        for (int i = 0; i < 192; i++) e[i * 96 + w] *= inv;
    }
    __syncthreads();
    int g = tid / 96;
    int w = tid - g * 96;
    float gam = __ldg(gamma);
    for (int cc = 0; cc < 64; cc++) {
        int c = g * 64 + cc;
        vr[g * 96 + w] = vb[(size_t)c * NPIX + h * Wd + w];
        __syncthreads();
        float oH = 0.f, oW = 0.f;
        const float* vcol = vb + (size_t)c * NPIX + w;
#pragma unroll 4
        for (int s = 0; s < 96; s++) {
            oH += vcol[s * Wd] * e[s * 96 + w];
            oW += vr[g * 96 + s] * e[(96 + s) * 96 + w];
        }
        size_t o = ((size_t)b * ICd + c) * NPIX + h * Wd + w;
        g_cca[o] = tf32r(gam * (oH + oW) + g_out1[o]);
        __syncthreads();
    }
}

// ---------------- CAM energy: exact fp32 NT split-K ----------------
__global__ void __launch_bounds__(256) egemm_nt(const float* __restrict__ x)
{
    int bz = blockIdx.z;
    int b = bz / KSPLIT, ks = bz - b * KSPLIT;
    const float* A = x + (size_t)b * Cc * NPIX;
    float* Cm = g_epart + (size_t)(ks * Bq + b) * Cc * Cc;
    int k0s = ks * ECHUNK, k0e = k0s + ECHUNK;

    __shared__ float As[8][132];
    __shared__ float Bs[8][132];

    int tid = threadIdx.x;
    int tx = tid & 15, ty = tid >> 4;
    int row0 = blockIdx.y * 128, col0 = blockIdx.x * 128;
    int ar = tid >> 1, ak = (tid & 1) * 4;
    const float* Aptr = A + (size_t)(row0 + ar) * NPIX + ak;
    const float* Bptr = A + (size_t)(col0 + ar) * NPIX + ak;

    float acc[8][8];
#pragma unroll
    for (int i = 0; i < 8; i++)
#pragma unroll
        for (int j = 0; j < 8; j++) acc[i][j] = 0.f;

    float4 pa = *(const float4*)(Aptr + k0s);
    float4 pb = *(const float4*)(Bptr + k0s);
    for (int k0 = k0s; k0 < k0e; k0 += 8) {
        As[ak + 0][ar] = pa.x; As[ak + 1][ar] = pa.y;
        As[ak + 2][ar] = pa.z; As[ak + 3][ar] = pa.w;
        Bs[ak + 0][ar] = pb.x; Bs[ak + 1][ar] = pb.y;
        Bs[ak + 2][ar] = pb.z; Bs[ak + 3][ar] = pb.w;
        __syncthreads();
        if (k0 + 8 < k0e) {
            pa = *(const float4*)(Aptr + k0 + 8);
            pb = *(const float4*)(Bptr + k0 + 8);
        }
#pragma unroll
        for (int kk = 0; kk < 8; kk++) {
            float4 a0 = *(const float4*)&As[kk][ty * 8];
            float4 a1 = *(const float4*)&As[kk][ty * 8 + 4];
            float4 b0 = *(const float4*)&Bs[kk][tx * 8];
            float4 b1 = *(const float4*)&Bs[kk][tx * 8 + 4];
            float av[8] = {a0.x, a0.y, a0.z, a0.w, a1.x, a1.y, a1.z, a1.w};
            float bv[8] = {b0.x, b0.y, b0.z, b0.w, b1.x, b1.y, b1.z, b1.w};
#pragma unroll
            for (int i = 0; i < 8; i++)
#pragma unroll
                for (int j = 0; j < 8; j++)
                    acc[i][j] += av[i] * bv[j];
        }
        __syncthreads();
    }
#pragma unroll
    for (int i = 0; i < 8; i++) {
        size_t off = (size_t)(row0 + ty * 8 + i) * Cc + col0 + tx * 8;
        *(float4*)&Cm[off] = make_float4(acc[i][0], acc[i][1], acc[i][2], acc[i][3]);
        *(float4*)&Cm[off + 4] = make_float4(acc[i][4], acc[i][5], acc[i][6], acc[i][7]);
    }
}

// ---------------- CAM softmax ----------------
__global__ void __launch_bounds__(128) cam_softmax_kernel()
{
    int b = blockIdx.y, c = blockIdx.x;
    int t = threadIdx.x;
    __shared__ float red[4];
    float4 v = make_float4(0.f, 0.f, 0.f, 0.f);
#pragma unroll
    for (int s = 0; s < KSPLIT; s++) {
        const float4 p = *(const float4*)&g_epart[(((size_t)(s * Bq + b)) * Cc + c) * Cc + t * 4];
        v.x += p.x; v.y += p.y; v.z += p.z; v.w += p.w;
    }
    float lmn = fminf(fminf(v.x, v.y), fminf(v.z, v.w));
#pragma unroll
    for (int o = 16; o; o >>= 1) lmn = fminf(lmn, __shfl_xor_sync(0xffffffffu, lmn, o));
    if ((t & 31) == 0) red[t >> 5] = lmn;
    __syncthreads();
    float mn = fminf(fminf(red[0], red[1]), fminf(red[2], red[3]));
    __syncthreads();
    float4 p;
    p.x = __expf(mn - v.x); p.y = __expf(mn - v.y);
    p.z = __expf(mn - v.z); p.w = __expf(mn - v.w);
    float ls = p.x + p.y + p.z + p.w;
#pragma unroll
    for (int o = 16; o; o >>= 1) ls += __shfl_xor_sync(0xffffffffu, ls, o);
    if ((t & 31) == 0) red[t >> 5] = ls;
    __syncthreads();
    float inv = 1.f / (red[0] + red[1] + red[2] + red[3]);
    p.x = tf32r(p.x * inv); p.y = tf32r(p.y * inv);
    p.z = tf32r(p.z * inv); p.w = tf32r(p.w * inv);
    *(float4*)&g_energy[((size_t)b * Cc + c) * Cc + t * 4] = p;
}

// ---------------- launch ----------------
extern "C" void kernel_launch(void* const* d_in, const int* in_sizes, int n_in,
                              void* d_out, int out_size)
{
    const float* x        = (const float*)d_in[0];
    const float* conva_w  = (const float*)d_in[1];
    const float* bn1_s    = (const float*)d_in[2];
    const float* bn1_b    = (const float*)d_in[3];
    const float* bn1_m    = (const float*)d_in[4];
    const float* bn1_v    = (const float*)d_in[5];
    const float* wq       = (const float*)d_in[6];
    const float* bq       = (const float*)d_in[7];
    const float* wk       = (const float*)d_in[8];
    const float* bk       = (const float*)d_in[9];
    const float* wv       = (const float*)d_in[10];
    const float* bv       = (const float*)d_in[11];
    const float* gamma_cca= (const float*)d_in[12];
    const float* convb_w  = (const float*)d_in[13];
    const float* bn2_s    = (const float*)d_in[14];
    const float* bn2_b    = (const float*)d_in[15];
    const float* bn2_m    = (const float*)d_in[16];
    const float* bn2_v    = (const float*)d_in[17];
    const float* bot_w1   = (const float*)d_in[18];
    const float* bn3_s    = (const float*)d_in[19];
    const float* bn3_b    = (const float*)d_in[20];
    const float* bn3_m    = (const float*)d_in[21];
    const float* bn3_v    = (const float*)d_in[22];
    const float* bot_w2   = (const float*)d_in[23];
    const float* bot_b2   = (const float*)d_in[24];
    const float* gamma_cam= (const float*)d_in[25];
    float* out = (float*)d_out;

    float *p_xr, *p_out1, *p_cca, *p_out2, *p_b1, *p_b2, *p_en;
    float *p_wta, *p_wtb, *p_wt1, *p_w2r;
    cudaGetSymbolAddress((void**)&p_xr, g_xr);
    cudaGetSymbolAddress((void**)&p_out1, g_out1);
    cudaGetSymbolAddress((void**)&p_cca, g_cca);
    cudaGetSymbolAddress((void**)&p_out2, g_out2);
    cudaGetSymbolAddress((void**)&p_b1, g_bott1);
    cudaGetSymbolAddress((void**)&p_b2, g_bott2);
    cudaGetSymbolAddress((void**)&p_en, g_energy);
    cudaGetSymbolAddress((void**)&p_wta, g_wta);
    cudaGetSymbolAddress((void**)&p_wtb, g_wtb);
    cudaGetSymbolAddress((void**)&p_wt1, g_wt1);
    cudaGetSymbolAddress((void**)&p_w2r, g_w2r);

    cudaFuncSetAttribute(cca2_kernel, cudaFuncAttributeMaxDynamicSharedMemorySize, 90112);

    // prep: tf32-rounded copies / transposes
    roundcopy4<<<512, 256>>>(x, p_xr, Bq * Cc * NPIX / 4);
    roundcopy4<<<64, 256>>>(bot_w2, p_w2r, Cc * Cc / 4);
    wtrans_tf32<<<256, 256>>>(conva_w, p_wta, Cc, ICd);
    wtrans_tf32<<<64, 256>>>(convb_w, p_wtb, ICd, ICd);
    wtrans_tf32<<<512, 256>>>(bot_w1, p_wt1, Cc + ICd, Cc);

    // 1) conva 512->128 (+bn1+relu, rounded)
    conv_tc<9, M_BNRELU, true><<<dim3(72, 1, Bq), 256>>>(
        p_xr, Cc, nullptr, 0, p_wta, 0, ICd, p_out1,
        bn1_s, bn1_b, bn1_m, bn1_v, nullptr, nullptr, nullptr);

    // 2) qkv
    qkv_kernel<<<dim3(NPIX / 64, Bq), 128>>>(wq, bq, wk, bk, wv, bv);

    // 3) cca (writes rounded g_cca)
    cca2_kernel<<<dim3(Hd, Bq), 192, 90112>>>(gamma_cca);

    // 4) convb 128->128 (+bn2+relu, rounded)
    conv_tc<9, M_BNRELU, true><<<dim3(72, 1, Bq), 256>>>(
        p_cca, ICd, nullptr, 0, p_wtb, 0, ICd, p_out2,
        bn2_s, bn2_b, bn2_m, bn2_v, nullptr, nullptr, nullptr);

    // 5) bot conv1 concat(x,out2) 640->512 (+bn3+relu, rounded)
    conv_tc<9, M_BNRELU, true><<<dim3(72, 4, Bq), 256>>>(
        p_xr, Cc, p_out2, ICd, p_wt1, 0, Cc, p_b1,
        bn3_s, bn3_b, bn3_m, bn3_v, nullptr, nullptr, nullptr);

    // 6) bot conv2 1x1 + bias -> g_bott2 (fp32)
    conv_tc<1, M_BIAS, false><<<dim3(72, 4, Bq), 256>>>(
        p_b1, Cc, nullptr, 0, p_w2r, 0, Cc, p_b2,
        bot_b2, nullptr, nullptr, nullptr, nullptr, nullptr, nullptr);

    // 7) CAM energy (exact fp32, split-K)
    egemm_nt<<<dim3(Cc / 128, Cc / 128, Bq * KSPLIT), 256>>>(x);

    // 8) CAM softmax -> g_energy (rounded attention)
    cam_softmax_kernel<<<dim3(Cc, Bq), 128>>>();

    // 9) final: out = bott2 + gamma*(att@xr) + x
    conv_tc<1, M_FINAL, false><<<dim3(72, 4, Bq), 256>>>(
        p_xr, Cc, nullptr, 0, p_en, (size_t)Cc * Cc, Cc, out,
        nullptr, nullptr, nullptr, nullptr, p_b2, x, gamma_cam);
}

// round 6
// speedup vs baseline: 3.4550x; 1.0264x over previous
#include <cuda_runtime.h>
#include <cstdint>

#define Bq 4
#define Cc 512
#define NPIX 9216
#define ICd 128
#define QCd 16
#define Hd 96
#define Wd 96
#define ESPLIT 4

// ---------------- scratch ----------------
__device__ float g_xr[(size_t)Bq * Cc * NPIX];    // tf32 hi part of x
__device__ float g_xlo[(size_t)Bq * Cc * NPIX];   // tf32 lo part of x
__device__ float g_out1[Bq * ICd * NPIX];
__device__ float g_q[Bq * QCd * NPIX];
__device__ float g_k[Bq * QCd * NPIX];
__device__ float g_v[Bq * ICd * NPIX];
__device__ float g_cca[Bq * ICd * NPIX];
__device__ float g_out2[Bq * ICd * NPIX];
__device__ float g_bott1[(size_t)Bq * Cc * NPIX];
__device__ float g_energy[Bq * Cc * Cc];
__device__ float g_epart[(size_t)ESPLIT * Bq * Cc * Cc];
__device__ float g_wta[9 * 128 * 512];
__device__ float g_wtb[9 * 128 * 128];
__device__ float g_wt1[9 * 512 * 640];
__device__ float g_w2r[512 * 512];

__device__ __forceinline__ float tf32r(float x) {
    uint32_t u;
    asm("cvt.rna.tf32.f32 %0, %1;" : "=r"(u) : "f"(x));
    return __uint_as_float(u);
}

__device__ __forceinline__ void mma1688(float* c, const uint32_t* a, const uint32_t* b) {
    asm volatile(
        "mma.sync.aligned.m16n8k8.row.col.f32.tf32.tf32.f32 "
        "{%0,%1,%2,%3}, {%4,%5,%6,%7}, {%8,%9}, {%0,%1,%2,%3};"
        : "+f"(c[0]), "+f"(c[1]), "+f"(c[2]), "+f"(c[3])
        : "r"(a[0]), "r"(a[1]), "r"(a[2]), "r"(a[3]), "r"(b[0]), "r"(b[1]));
}

// ---------------- prep ----------------
__global__ void splitcopy4(const float* __restrict__ s, float* __restrict__ dh,
                           float* __restrict__ dl, int n4) {
    for (int i = blockIdx.x * blockDim.x + threadIdx.x; i < n4; i += gridDim.x * blockDim.x) {
        float4 v = ((const float4*)s)[i];
        float4 h, l;
        h.x = tf32r(v.x); l.x = tf32r(v.x - h.x);
        h.y = tf32r(v.y); l.y = tf32r(v.y - h.y);
        h.z = tf32r(v.z); l.z = tf32r(v.z - h.z);
        h.w = tf32r(v.w); l.w = tf32r(v.w - h.w);
        ((float4*)dh)[i] = h;
        ((float4*)dl)[i] = l;
    }
}
__global__ void roundcopy4(const float* __restrict__ s, float* __restrict__ d, int n4) {
    for (int i = blockIdx.x * blockDim.x + threadIdx.x; i < n4; i += gridDim.x * blockDim.x) {
        float4 v = ((const float4*)s)[i];
        v.x = tf32r(v.x); v.y = tf32r(v.y); v.z = tf32r(v.z); v.w = tf32r(v.w);
        ((float4*)d)[i] = v;
    }
}
__global__ void wtrans_tf32(const float* __restrict__ src, float* __restrict__ dst,
                            int CIN, int OC) {
    int n = OC * CIN * 9;
    for (int i = blockIdx.x * blockDim.x + threadIdx.x; i < n; i += gridDim.x * blockDim.x) {
        int oc = i / (CIN * 9);
        int rem = i - oc * (CIN * 9);
        int ic = rem / 9;
        int tap = rem - ic * 9;
        dst[((size_t)tap * OC + oc) * CIN + ic] = tf32r(src[i]);
    }
}

// ---------------- tf32 TC implicit-GEMM conv (+BN+ReLU) ----------------
// C[oc][px] = sum_k A[oc][k]*B[k][px]; k = tap*CIN+ic. CTA 128x128, BK=16.
template<int NTAPS, bool ROUND>
__global__ void __launch_bounds__(256, 2) conv_tc(
    const float* __restrict__ in1, int cin1,
    const float* __restrict__ in2, int cin2,
    const float* __restrict__ Aw, int OCtot,
    float* __restrict__ outp,
    const float* __restrict__ q0, const float* __restrict__ q1,
    const float* __restrict__ q2, const float* __restrict__ q3)
{
    const int CIN = cin1 + cin2;
    const int NCHUNK = (NTAPS * CIN) / 16;

    __shared__ float As[2][128][20];
    __shared__ float Bs[2][16][132];

    int tid = threadIdx.x, lane = tid & 31, wid = tid >> 5;
    int wm = (wid & 1) * 64, wn = (wid >> 1) * 32;
    int px0 = blockIdx.x * 128;
    int oc0 = blockIdx.y * 128;
    int b = blockIdx.z;
    in1 += (size_t)b * cin1 * NPIX;
    if (cin2 > 0) in2 += (size_t)b * cin2 * NPIX;
    outp += (size_t)b * OCtot * NPIX;

    int arow = tid >> 1, akq = (tid & 1) * 8;

    // hoisted B-load coordinates (constant per thread)
    int hB[8], wB[8], kB[8], pxB[8];
#pragma unroll
    for (int l = 0; l < 8; l++) {
        int idx = tid + l * 256;
        kB[l] = idx >> 7;
        int j = idx & 127;
        int px = px0 + j;
        pxB[l] = px;
        hB[l] = px / 96;
        wB[l] = px - hB[l] * 96;
    }

    float4 pa0, pa1;
    float pb[8];

    auto loadA = [&](int c) {
        int ko = c * 16;
        int tap = (NTAPS == 9) ? ko / CIN : 0;
        int ic = ko - tap * CIN;
        const float* ap = Aw + ((size_t)tap * OCtot + oc0 + arow) * CIN + ic + akq;
        pa0 = *(const float4*)ap;
        pa1 = *(const float4*)(ap + 4);
    };
    auto loadB = [&](int c) {
        int ko = c * 16;
        int tap = (NTAPS == 9) ? ko / CIN : 0;
        int ic = ko - tap * CIN;
        int dh = (NTAPS == 9) ? tap / 3 - 1 : 0;
        int dw = (NTAPS == 9) ? tap % 3 - 1 : 0;
        int doff = dh * 96 + dw;
#pragma unroll
        for (int l = 0; l < 8; l++) {
            int ch = ic + kB[l];
            const float* src = (ch < cin1) ? (in1 + (size_t)ch * NPIX)
                                           : (in2 + (size_t)(ch - cin1) * NPIX);
            float v;
            if (NTAPS == 9) {
                int hh = hB[l] + dh, ww = wB[l] + dw;
                bool ok = ((unsigned)hh < 96u) && ((unsigned)ww < 96u);
                v = ok ? __ldg(src + pxB[l] + doff) : 0.f;
            } else {
                v = __ldg(src + pxB[l]);
            }
            pb[l] = v;
        }
    };
    auto storeAB = [&](int s) {
        *(float4*)&As[s][arow][akq] = pa0;
        *(float4*)&As[s][arow][akq + 4] = pa1;
#pragma unroll
        for (int l = 0; l < 8; l++) {
            int idx = tid + l * 256;
            Bs[s][idx >> 7][idx & 127] = pb[l];
        }
    };

    float acc[4][4][4];
#pragma unroll
    for (int i = 0; i < 4; i++)
#pragma unroll
        for (int j = 0; j < 4; j++)
#pragma unroll
            for (int r = 0; r < 4; r++) acc[i][j][r] = 0.f;

    loadA(0); loadB(0); storeAB(0);
    __syncthreads();

    for (int c = 0; c < NCHUNK; c++) {
        int s = c & 1;
        if (c + 1 < NCHUNK) { loadA(c + 1); loadB(c + 1); }
#pragma unroll
        for (int kk = 0; kk < 16; kk += 8) {
            uint32_t af[4][4], bf[4][2];
            int kq = kk + (lane & 3);
            int g4 = lane >> 2;
#pragma unroll
            for (int i = 0; i < 4; i++) {
                int m = wm + i * 16 + g4;
                af[i][0] = __float_as_uint(As[s][m][kq]);
                af[i][1] = __float_as_uint(As[s][m + 8][kq]);
                af[i][2] = __float_as_uint(As[s][m][kq + 4]);
                af[i][3] = __float_as_uint(As[s][m + 8][kq + 4]);
            }
#pragma unroll
            for (int j = 0; j < 4; j++) {
                int n = wn + j * 8 + g4;
                bf[j][0] = __float_as_uint(Bs[s][kq][n]);
                bf[j][1] = __float_as_uint(Bs[s][kq + 4][n]);
            }
#pragma unroll
            for (int i = 0; i < 4; i++)
#pragma unroll
                for (int j = 0; j < 4; j++)
                    mma1688(acc[i][j], af[i], bf[j]);
        }
        if (c + 1 < NCHUNK) storeAB(s ^ 1);
        __syncthreads();
    }

#pragma unroll
    for (int i = 0; i < 4; i++) {
#pragma unroll
        for (int hh = 0; hh < 2; hh++) {
            int row = oc0 + wm + i * 16 + (lane >> 2) + hh * 8;
            float inv = __ldg(q0 + row) * rsqrtf(__ldg(q3 + row) + 1e-5f);
            float add = __ldg(q1 + row) - __ldg(q2 + row) * inv;
#pragma unroll
            for (int j = 0; j < 4; j++) {
                int col = px0 + wn + j * 8 + (lane & 3) * 2;
                size_t off = (size_t)row * NPIX + col;
                float v0 = fmaxf(acc[i][j][hh * 2 + 0] * inv + add, 0.f);
                float v1 = fmaxf(acc[i][j][hh * 2 + 1] * inv + add, 0.f);
                if (ROUND) { v0 = tf32r(v0); v1 = tf32r(v1); }
                *(float2*)(outp + off) = make_float2(v0, v1);
            }
        }
    }
}

// ---------------- final fused kernel: out = W2*bott1 + b2 + att'*xr + x ----------------
__global__ void __launch_bounds__(256, 2) final_tc(
    const float* __restrict__ xexact, const float* __restrict__ b2,
    float* __restrict__ outp)
{
    __shared__ float As[2][128][20];
    __shared__ float Bs[2][16][132];

    int tid = threadIdx.x, lane = tid & 31, wid = tid >> 5;
    int wm = (wid & 1) * 64, wn = (wid >> 1) * 32;
    int px0 = blockIdx.x * 128;
    int oc0 = blockIdx.y * 128;
    int b = blockIdx.z;
    const float* B1 = g_bott1 + (size_t)b * Cc * NPIX;
    const float* B2 = g_xr + (size_t)b * Cc * NPIX;
    const float* A2 = g_energy + (size_t)b * Cc * Cc;
    const float* xb = xexact + (size_t)b * Cc * NPIX;
    outp += (size_t)b * Cc * NPIX;

    int arow = tid >> 1, akq = (tid & 1) * 8;
    int kB[8], pxB[8];
#pragma unroll
    for (int l = 0; l < 8; l++) {
        int idx = tid + l * 256;
        kB[l] = idx >> 7;
        pxB[l] = px0 + (idx & 127);
    }

    float4 pa0, pa1;
    float pb[8];
    auto loadA = [&](int c) {
        int p = c >> 5;
        int ic = (c - (p << 5)) * 16;
        const float* base = p ? A2 : g_w2r;
        const float* ap = base + (size_t)(oc0 + arow) * Cc + ic + akq;
        pa0 = *(const float4*)ap;
        pa1 = *(const float4*)(ap + 4);
    };
    auto loadB = [&](int c) {
        int p = c >> 5;
        int ic = (c - (p << 5)) * 16;
        const float* src = p ? B2 : B1;
#pragma unroll
        for (int l = 0; l < 8; l++)
            pb[l] = __ldg(src + (size_t)(ic + kB[l]) * NPIX + pxB[l]);
    };
    auto storeAB = [&](int s) {
        *(float4*)&As[s][arow][akq] = pa0;
        *(float4*)&As[s][arow][akq + 4] = pa1;
#pragma unroll
        for (int l = 0; l < 8; l++) {
            int idx = tid + l * 256;
            Bs[s][idx >> 7][idx & 127] = pb[l];
        }
    };

    float acc[4][4][4];
#pragma unroll
    for (int i = 0; i < 4; i++)
#pragma unroll
        for (int j = 0; j < 4; j++)
#pragma unroll
            for (int r = 0; r < 4; r++) acc[i][j][r] = 0.f;

    loadA(0); loadB(0); storeAB(0);
    __syncthreads();

    const int NCHUNK = 64;
    for (int c = 0; c < NCHUNK; c++) {
        int s = c & 1;
        if (c + 1 < NCHUNK) { loadA(c + 1); loadB(c + 1); }
#pragma unroll
        for (int kk = 0; kk < 16; kk += 8) {
            uint32_t af[4][4], bf[4][2];
            int kq = kk + (lane & 3);
            int g4 = lane >> 2;
#pragma unroll
            for (int i = 0; i < 4; i++) {
                int m = wm + i * 16 + g4;
                af[i][0] = __float_as_uint(As[s][m][kq]);
                af[i][1] = __float_as_uint(As[s][m + 8][kq]);
                af[i][2] = __float_as_uint(As[s][m][kq + 4]);
                af[i][3] = __float_as_uint(As[s][m + 8][kq + 4]);
            }
#pragma unroll
            for (int j = 0; j < 4; j++) {
                int n = wn + j * 8 + g4;
                bf[j][0] = __float_as_uint(Bs[s][kq][n]);
                bf[j][1] = __float_as_uint(Bs[s][kq + 4][n]);
            }
#pragma unroll
            for (int i = 0; i < 4; i++)
#pragma unroll
                for (int j = 0; j < 4; j++)
                    mma1688(acc[i][j], af[i], bf[j]);
        }
        if (c + 1 < NCHUNK) storeAB(s ^ 1);
        __syncthreads();
    }

#pragma unroll
    for (int i = 0; i < 4; i++) {
#pragma unroll
        for (int hh = 0; hh < 2; hh++) {
            int row = oc0 + wm + i * 16 + (lane >> 2) + hh * 8;
            float add = __ldg(b2 + row);
#pragma unroll
            for (int j = 0; j < 4; j++) {
                int col = px0 + wn + j * 8 + (lane & 3) * 2;
                size_t off = (size_t)row * NPIX + col;
                float2 xv = *(const float2*)(xb + off);
                *(float2*)(outp + off) = make_float2(
                    acc[i][j][hh * 2 + 0] + add + xv.x,
                    acc[i][j][hh * 2 + 1] + add + xv.y);
            }
        }
    }
}

// ---------------- CAM energy: 3xTF32 tensor-core, split-K ----------------
__global__ void __launch_bounds__(256, 2) egemm_tc()
{
    __shared__ float Ah[128][20], Al[128][20], Bh[128][20], Bl[128][20];

    int bz = blockIdx.z;
    int b = bz / ESPLIT, ks = bz - b * ESPLIT;
    const float* xh = g_xr + (size_t)b * Cc * NPIX;
    const float* xl = g_xlo + (size_t)b * Cc * NPIX;
    float* Cm = g_epart + (size_t)(ks * Bq + b) * Cc * Cc;
    const int KCH = NPIX / ESPLIT;
    int k0s = ks * KCH, k0e = k0s + KCH;

    int tid = threadIdx.x, lane = tid & 31, wid = tid >> 5;
    int wm = (wid & 1) * 64, wn = (wid >> 1) * 32;
    int row0 = blockIdx.y * 128, col0 = blockIdx.x * 128;
    int ar = tid >> 1, ak = (tid & 1) * 8;
    const float* Arh = xh + (size_t)(row0 + ar) * NPIX + ak;
    const float* Arl = xl + (size_t)(row0 + ar) * NPIX + ak;
    const float* Brh = xh + (size_t)(col0 + ar) * NPIX + ak;
    const float* Brl = xl + (size_t)(col0 + ar) * NPIX + ak;

    float acc[4][4][4];
#pragma unroll
    for (int i = 0; i < 4; i++)
#pragma unroll
        for (int j = 0; j < 4; j++)
#pragma unroll
            for (int r = 0; r < 4; r++) acc[i][j][r] = 0.f;

    for (int k0 = k0s; k0 < k0e; k0 += 16) {
        __syncthreads();
        *(float4*)&Ah[ar][ak]     = *(const float4*)(Arh + k0);
        *(float4*)&Ah[ar][ak + 4] = *(const float4*)(Arh + k0 + 4);
        *(float4*)&Al[ar][ak]     = *(const float4*)(Arl + k0);
        *(float4*)&Al[ar][ak + 4] = *(const float4*)(Arl + k0 + 4);
        *(float4*)&Bh[ar][ak]     = *(const float4*)(Brh + k0);
        *(float4*)&Bh[ar][ak + 4] = *(const float4*)(Brh + k0 + 4);
        *(float4*)&Bl[ar][ak]     = *(const float4*)(Brl + k0);
        *(float4*)&Bl[ar][ak + 4] = *(const float4*)(Brl + k0 + 4);
        __syncthreads();
#pragma unroll
        for (int kk = 0; kk < 16; kk += 8) {
            int kq = kk + (lane & 3);
            int g4 = lane >> 2;
            uint32_t ah[4][4], al[4][4];
#pragma unroll
            for (int i = 0; i < 4; i++) {
                int m = wm + i * 16 + g4;
                ah[i][0] = __float_as_uint(Ah[m][kq]);
                ah[i][1] = __float_as_uint(Ah[m + 8][kq]);
                ah[i][2] = __float_as_uint(Ah[m][kq + 4]);
                ah[i][3] = __float_as_uint(Ah[m + 8][kq + 4]);
                al[i][0] = __float_as_uint(Al[m][kq]);
                al[i][1] = __float_as_uint(Al[m + 8][kq]);
                al[i][2] = __float_as_uint(Al[m][kq + 4]);
                al[i][3] = __float_as_uint(Al[m + 8][kq + 4]);
            }
#pragma unroll
            for (int j = 0; j < 4; j++) {
                int n = wn + j * 8 + g4;
                uint32_t bh[2], bl[2];
                bh[0] = __float_as_uint(Bh[n][kq]);
                bh[1] = __float_as_uint(Bh[n][kq + 4]);
                bl[0] = __float_as_uint(Bl[n][kq]);
                bl[1] = __float_as_uint(Bl[n][kq + 4]);
#pragma unroll
                for (int i = 0; i < 4; i++) {
                    mma1688(acc[i][j], ah[i], bh);
                    mma1688(acc[i][j], ah[i], bl);
                    mma1688(acc[i][j], al[i], bh);
                }
            }
        }
    }

#pragma unroll
    for (int i = 0; i < 4; i++) {
#pragma unroll
        for (int hh = 0; hh < 2; hh++) {
            int row = row0 + wm + i * 16 + (lane >> 2) + hh * 8;
#pragma unroll
            for (int j = 0; j < 4; j++) {
                int col = col0 + wn + j * 8 + (lane & 3) * 2;
                *(float2*)&Cm[(size_t)row * Cc + col] = make_float2(
                    acc[i][j][hh * 2 + 0], acc[i][j][hh * 2 + 1]);
            }
        }
    }
}

// ---------------- q/k/v 1x1 convs ----------------
__global__ void __launch_bounds__(128) qkv_kernel(
    const float* __restrict__ wq, const float* __restrict__ bq,
    const float* __restrict__ wk, const float* __restrict__ bk,
    const float* __restrict__ wv, const float* __restrict__ bv)
{
    int b = blockIdx.y;
    int px0 = blockIdx.x * 64;
    int t = threadIdx.x;
    int px = t & 63;
    int half = t >> 6;
    __shared__ float xs[128][64];
    for (int idx = t; idx < 128 * 64; idx += 128) {
        int ic = idx >> 6, p = idx & 63;
        xs[ic][p] = g_out1[((size_t)b * ICd + ic) * NPIX + px0 + p];
    }
    __syncthreads();
    for (int oc = half * 80; oc < half * 80 + 80; oc++) {
        const float* wrow; float bias; float* dst;
        if (oc < 16) { wrow = wq + oc * 128; bias = bq[oc];
                       dst = g_q + ((size_t)b * QCd + oc) * NPIX; }
        else if (oc < 32) { int o = oc - 16; wrow = wk + o * 128; bias = bk[o];
                            dst = g_k + ((size_t)b * QCd + o) * NPIX; }
        else { int o = oc - 32; wrow = wv + o * 128; bias = bv[o];
               dst = g_v + ((size_t)b * ICd + o) * NPIX; }
        float a = bias;
#pragma unroll 8
        for (int ic = 0; ic < 128; ic += 4) {
            float4 w4 = *(const float4*)(wrow + ic);
            a += w4.x * xs[ic][px] + w4.y * xs[ic + 1][px]
               + w4.z * xs[ic + 2][px] + w4.w * xs[ic + 3][px];
        }
        dst[px0 + px] = a;
    }
}

// ---------------- criss-cross attention ----------------
__global__ void __launch_bounds__(192) cca2_kernel(const float* __restrict__ gamma)
{
    extern __shared__ float sm[];
    float* e = sm;
    float* qs = sm + 192 * 96;
    float* ks_ = qs + 16 * 96;
    float* vr = ks_ + 16 * 96;

    int h = blockIdx.x, b = blockIdx.y;
    int tid = threadIdx.x;
    const float* qb = g_q + (size_t)b * QCd * NPIX;
    const float* kb = g_k + (size_t)b * QCd * NPIX;
    const float* vb = g_v + (size_t)b * ICd * NPIX;

    for (int idx = tid; idx < 16 * 96; idx += 192) {
        int c = idx / 96, w = idx - c * 96;
        qs[c * 96 + w] = qb[c * NPIX + h * Wd + w];
        ks_[c * 96 + w] = kb[c * NPIX + h * Wd + w];
    }
    __syncthreads();
    for (int idx = tid; idx < 96 * 96; idx += 192) {
        int s = idx / 96, w = idx - s * 96;
        float a = 0.f;
#pragma unroll
        for (int c = 0; c < 16; c++) a += qs[c * 96 + w] * ks_[c * 96 + s];
        e[(96 + s) * 96 + w] = a;
    }
    for (int idx = tid; idx < 96 * 96; idx += 192) {
        int s = idx / 96, w = idx - s * 96;
        float a = 0.f;
#pragma unroll
        for (int c = 0; c < 16; c++) a += qs[c * 96 + w] * kb[c * NPIX + s * Wd + w];
        e[s * 96 + w] = (s == h) ? -1e30f : a;
    }
    __syncthreads();
    if (tid < 96) {
        int w = tid;
        float M = -1e30f;
        for (int i = 0; i < 192; i++) M = fmaxf(M, e[i * 96 + w]);
        float S = 0.f;
        for (int i = 0; i < 192; i++) {
            float p = __expf(e[i * 96 + w] - M);
            e[i * 96 + w] = p; S += p;
        }
        float inv = 1.f / S;
        for (int i = 0; i < 192; i++) e[i * 96 + w] *= inv;
    }
    __syncthreads();
    int g = tid / 96;
    int w = tid - g * 96;
    float gam = __ldg(gamma);
    for (int cc = 0; cc < 64; cc++) {
        int c = g * 64 + cc;
        vr[g * 96 + w] = vb[(size_t)c * NPIX + h * Wd + w];
        __syncthreads();
        float oH = 0.f, oW = 0.f;
        const float* vcol = vb + (size_t)c * NPIX + w;
#pragma unroll 4
        for (int s = 0; s < 96; s++) {
            oH += vcol[s * Wd] * e[s * 96 + w];
            oW += vr[g * 96 + s] * e[(96 + s) * 96 + w];
        }
        size_t o = ((size_t)b * ICd + c) * NPIX + h * Wd + w;
        g_cca[o] = tf32r(gam * (oH + oW) + g_out1[o]);
        __syncthreads();
    }
}

// ---------------- CAM softmax (sums partials, scales by gamma_cam) ----------------
__global__ void __launch_bounds__(128) cam_softmax_kernel(const float* __restrict__ gma)
{
    int b = blockIdx.y, c = blockIdx.x;
    int t = threadIdx.x;
    __shared__ float red[4];
    float4 v = make_float4(0.f, 0.f, 0.f, 0.f);
#pragma unroll
    for (int s = 0; s < ESPLIT; s++) {
        const float4 p = *(const float4*)&g_epart[(((size_t)(s * Bq + b)) * Cc + c) * Cc + t * 4];
        v.x += p.x; v.y += p.y; v.z += p.z; v.w += p.w;
    }
    float lmn = fminf(fminf(v.x, v.y), fminf(v.z, v.w));
#pragma unroll
    for (int o = 16; o; o >>= 1) lmn = fminf(lmn, __shfl_xor_sync(0xffffffffu, lmn, o));
    if ((t & 31) == 0) red[t >> 5] = lmn;
    __syncthreads();
    float mn = fminf(fminf(red[0], red[1]), fminf(red[2], red[3]));
    __syncthreads();
    float4 p;
    p.x = __expf(mn - v.x); p.y = __expf(mn - v.y);
    p.z = __expf(mn - v.z); p.w = __expf(mn - v.w);
    float ls = p.x + p.y + p.z + p.w;
#pragma unroll
    for (int o = 16; o; o >>= 1) ls += __shfl_xor_sync(0xffffffffu, ls, o);
    if ((t & 31) == 0) red[t >> 5] = ls;
    __syncthreads();
    float gam = __ldg(gma);
    float inv = gam / (red[0] + red[1] + red[2] + red[3]);
    p.x = tf32r(p.x * inv); p.y = tf32r(p.y * inv);
    p.z = tf32r(p.z * inv); p.w = tf32r(p.w * inv);
    *(float4*)&g_energy[((size_t)b * Cc + c) * Cc + t * 4] = p;
}

// ---------------- launch ----------------
extern "C" void kernel_launch(void* const* d_in, const int* in_sizes, int n_in,
                              void* d_out, int out_size)
{
    const float* x        = (const float*)d_in[0];
    const float* conva_w  = (const float*)d_in[1];
    const float* bn1_s    = (const float*)d_in[2];
    const float* bn1_b    = (const float*)d_in[3];
    const float* bn1_m    = (const float*)d_in[4];
    const float* bn1_v    = (const float*)d_in[5];
    const float* wq       = (const float*)d_in[6];
    const float* bq       = (const float*)d_in[7];
    const float* wk       = (const float*)d_in[8];
    const float* bk       = (const float*)d_in[9];
    const float* wv       = (const float*)d_in[10];
    const float* bv       = (const float*)d_in[11];
    const float* gamma_cca= (const float*)d_in[12];
    const float* convb_w  = (const float*)d_in[13];
    const float* bn2_s    = (const float*)d_in[14];
    const float* bn2_b    = (const float*)d_in[15];
    const float* bn2_m    = (const float*)d_in[16];
    const float* bn2_v    = (const float*)d_in[17];
    const float* bot_w1   = (const float*)d_in[18];
    const float* bn3_s    = (const float*)d_in[19];
    const float* bn3_b    = (const float*)d_in[20];
    const float* bn3_m    = (const float*)d_in[21];
    const float* bn3_v    = (const float*)d_in[22];
    const float* bot_w2   = (const float*)d_in[23];
    const float* bot_b2   = (const float*)d_in[24];
    const float* gamma_cam= (const float*)d_in[25];
    float* out = (float*)d_out;

    float *p_xr, *p_xlo, *p_cca, *p_b1, *p_wta, *p_wtb, *p_wt1, *p_w2r, *p_out1, *p_out2;
    cudaGetSymbolAddress((void**)&p_xr, g_xr);
    cudaGetSymbolAddress((void**)&p_xlo, g_xlo);
    cudaGetSymbolAddress((void**)&p_cca, g_cca);
    cudaGetSymbolAddress((void**)&p_b1, g_bott1);
    cudaGetSymbolAddress((void**)&p_wta, g_wta);
    cudaGetSymbolAddress((void**)&p_wtb, g_wtb);
    cudaGetSymbolAddress((void**)&p_wt1, g_wt1);
    cudaGetSymbolAddress((void**)&p_w2r, g_w2r);
    cudaGetSymbolAddress((void**)&p_out1, g_out1);
    cudaGetSymbolAddress((void**)&p_out2, g_out2);

    cudaFuncSetAttribute(cca2_kernel, cudaFuncAttributeMaxDynamicSharedMemorySize, 90112);

    // prep
    splitcopy4<<<512, 256>>>(x, p_xr, p_xlo, Bq * Cc * NPIX / 4);
    roundcopy4<<<64, 256>>>(bot_w2, p_w2r, Cc * Cc / 4);
    wtrans_tf32<<<256, 256>>>(conva_w, p_wta, Cc, ICd);
    wtrans_tf32<<<64, 256>>>(convb_w, p_wtb, ICd, ICd);
    wtrans_tf32<<<512, 256>>>(bot_w1, p_wt1, Cc + ICd, Cc);

    // 1) conva 512->128 (+bn1+relu, rounded)
    conv_tc<9, true><<<dim3(72, 1, Bq), 256>>>(
        p_xr, Cc, nullptr, 0, p_wta, ICd, p_out1,
        bn1_s, bn1_b, bn1_m, bn1_v);

    // 2) qkv
    qkv_kernel<<<dim3(NPIX / 64, Bq), 128>>>(wq, bq, wk, bk, wv, bv);

    // 3) cca
    cca2_kernel<<<dim3(Hd, Bq), 192, 90112>>>(gamma_cca);

    // 4) convb 128->128 (+bn2+relu, rounded)
    conv_tc<9, true><<<dim3(72, 1, Bq), 256>>>(
        p_cca, ICd, nullptr, 0, p_wtb, ICd, p_out2,
        bn2_s, bn2_b, bn2_m, bn2_v);

    // 5) bot conv1 concat(x,out2) 640->512 (+bn3+relu, rounded)
    conv_tc<9, true><<<dim3(72, 4, Bq), 256>>>(
        p_xr, Cc, p_out2, ICd, p_wt1, Cc, p_b1,
        bn3_s, bn3_b, bn3_m, bn3_v);

    // 6) CAM energy (3xTF32 tensor core, split-K)
    egemm_tc<<<dim3(Cc / 128, Cc / 128, Bq * ESPLIT), 256>>>();

    // 7) CAM softmax -> g_energy (gamma-scaled attention)
    cam_softmax_kernel<<<dim3(Cc, Bq), 128>>>(gamma_cam);

    // 8) final fused: out = W2*bott1 + b2 + att'*xr + x
    final_tc<<<dim3(72, 4, Bq), 256>>>(x, bot_b2, out);
}

// round 8
// speedup vs baseline: 3.8114x; 1.1031x over previous
#include <cuda_runtime.h>
#include <cstdint>

#define Bq 4
#define Cc 512
#define NPIX 9216
#define ICd 128
#define QCd 16
#define Hd 96
#define Wd 96
#define ESPLIT 4

// ---------------- scratch ----------------
__device__ float g_xr[(size_t)Bq * Cc * NPIX];    // tf32 hi part of x
__device__ float g_xlo[(size_t)Bq * Cc * NPIX];   // tf32 lo part of x
__device__ float g_out1[Bq * ICd * NPIX];
__device__ float g_q[Bq * QCd * NPIX];
__device__ float g_k[Bq * QCd * NPIX];
__device__ float g_v[Bq * ICd * NPIX];
__device__ float g_cca[Bq * ICd * NPIX];
__device__ float g_out2[Bq * ICd * NPIX];
__device__ float g_bott1[(size_t)Bq * Cc * NPIX];
__device__ float g_energy[Bq * Cc * Cc];
__device__ float g_epart[(size_t)ESPLIT * Bq * Cc * Cc];
__device__ float g_wta[9 * 128 * 512];
__device__ float g_wtb[9 * 128 * 128];
__device__ float g_wt1[9 * 512 * 640];
__device__ float g_w2r[512 * 512];

__device__ __forceinline__ float tf32r(float x) {
    uint32_t u;
    asm("cvt.rna.tf32.f32 %0, %1;" : "=r"(u) : "f"(x));
    return __uint_as_float(u);
}

__device__ __forceinline__ void mma1688(float* c, const uint32_t* a, const uint32_t* b) {
    asm volatile(
        "mma.sync.aligned.m16n8k8.row.col.f32.tf32.tf32.f32 "
        "{%0,%1,%2,%3}, {%4,%5,%6,%7}, {%8,%9}, {%0,%1,%2,%3};"
        : "+f"(c[0]), "+f"(c[1]), "+f"(c[2]), "+f"(c[3])
        : "r"(a[0]), "r"(a[1]), "r"(a[2]), "r"(a[3]), "r"(b[0]), "r"(b[1]));
}

// ---------------- prep ----------------
__global__ void splitcopy4(const float* __restrict__ s, float* __restrict__ dh,
                           float* __restrict__ dl, int n4) {
    for (int i = blockIdx.x * blockDim.x + threadIdx.x; i < n4; i += gridDim.x * blockDim.x) {
        float4 v = ((const float4*)s)[i];
        float4 h, l;
        h.x = tf32r(v.x); l.x = tf32r(v.x - h.x);
        h.y = tf32r(v.y); l.y = tf32r(v.y - h.y);
        h.z = tf32r(v.z); l.z = tf32r(v.z - h.z);
        h.w = tf32r(v.w); l.w = tf32r(v.w - h.w);
        ((float4*)dh)[i] = h;
        ((float4*)dl)[i] = l;
    }
}

// fused weight prep: wta, wtb, wt1 transposes + w2 round
__global__ void prep_weights(const float* __restrict__ wa, const float* __restrict__ wb,
                             const float* __restrict__ w1, const float* __restrict__ w2)
{
    const int n1 = 128 * 512 * 9;          // conva
    const int n2 = 128 * 128 * 9;          // convb
    const int n3 = 512 * 640 * 9;          // bot1
    const int n4 = 512 * 512;              // w2
    const int ntot = n1 + n2 + n3 + n4;
    for (int i = blockIdx.x * blockDim.x + threadIdx.x; i < ntot; i += gridDim.x * blockDim.x) {
        if (i < n1) {
            int oc = i / (512 * 9);
            int rem = i - oc * (512 * 9);
            int ic = rem / 9, tap = rem - ic * 9;
            g_wta[((size_t)tap * 128 + oc) * 512 + ic] = tf32r(wa[i]);
        } else if (i < n1 + n2) {
            int j = i - n1;
            int oc = j / (128 * 9);
            int rem = j - oc * (128 * 9);
            int ic = rem / 9, tap = rem - ic * 9;
            g_wtb[((size_t)tap * 128 + oc) * 128 + ic] = tf32r(wb[j]);
        } else if (i < n1 + n2 + n3) {
            int j = i - n1 - n2;
            int oc = j / (640 * 9);
            int rem = j - oc * (640 * 9);
            int ic = rem / 9, tap = rem - ic * 9;
            g_wt1[((size_t)tap * 512 + oc) * 640 + ic] = tf32r(w1[j]);
        } else {
            int j = i - n1 - n2 - n3;
            g_w2r[j] = tf32r(w2[j]);
        }
    }
}

// ---------------- tf32 TC implicit-GEMM conv (+BN+ReLU) ----------------
// CTA: 128 oc x 256 px, BK=16, 8 warps of 64x64. A in perm-K layout (LDS.128 frags).
#define ASTRIDE 20
#define ASTG (128 * ASTRIDE)
#define BSTRIDE 260
#define BSTG (16 * BSTRIDE)
#define CONV_SMEM ((2 * ASTG + 2 * BSTG) * 4)

template<int NTAPS, bool ROUND>
__global__ void __launch_bounds__(256, 1) conv_tc(
    const float* __restrict__ in1, int cin1,
    const float* __restrict__ in2, int cin2,
    const float* __restrict__ Aw, int OCtot,
    float* __restrict__ outp,
    const float* __restrict__ q0, const float* __restrict__ q1,
    const float* __restrict__ q2, const float* __restrict__ q3)
{
    const int CIN = cin1 + cin2;
    const int NCHUNK = (NTAPS * CIN) / 16;

    extern __shared__ float dsm[];
    float* Asm = dsm;                 // [2][128*ASTRIDE]
    float* Bsm = dsm + 2 * ASTG;      // [2][16*BSTRIDE]

    int tid = threadIdx.x, lane = tid & 31, wid = tid >> 5;
    int wm = (wid & 1) * 64, wn = (wid >> 1) * 64;
    int px0 = blockIdx.x * 256;
    int oc0 = blockIdx.y * 128;
    int b = blockIdx.z;
    in1 += (size_t)b * cin1 * NPIX;
    if (cin2 > 0) in2 += (size_t)b * cin2 * NPIX;
    outp += (size_t)b * OCtot * NPIX;

    int arow = tid >> 1, ahalf = tid & 1;
    int px = px0 + tid;
    int ph = px / 96, pw = px - ph * 96;

    float4 pa0, pa1;
    float pb[16];

    auto loadA = [&](int c) {
        int ko = c * 16;
        int tap = (NTAPS == 9) ? ko / CIN : 0;
        int ic = ko - tap * CIN;
        const float* ap = Aw + ((size_t)tap * OCtot + oc0 + arow) * CIN + ic + ahalf * 8;
        pa0 = *(const float4*)ap;
        pa1 = *(const float4*)(ap + 4);
    };
    auto loadB = [&](int c) {
        int ko = c * 16;
        int tap = (NTAPS == 9) ? ko / CIN : 0;
        int ic = ko - tap * CIN;
        const float* src = (ic < cin1) ? (in1 + (size_t)ic * NPIX)
                                       : (in2 + (size_t)(ic - cin1) * NPIX);
        if (NTAPS == 9) {
            int dh = tap / 3 - 1, dw = tap % 3 - 1;
            int hh = ph + dh, ww = pw + dw;
            bool ok = ((unsigned)hh < 96u) && ((unsigned)ww < 96u);
            const float* sp = src + px + dh * 96 + dw;
#pragma unroll
            for (int k = 0; k < 16; k++)
                pb[k] = ok ? __ldg(sp + (size_t)k * NPIX) : 0.f;
        } else {
#pragma unroll
            for (int k = 0; k < 16; k++)
                pb[k] = __ldg(src + (size_t)k * NPIX + px);
        }
    };
    auto storeAB = [&](int s) {
        // A perm store: pairs (k, k+4) -> adjacent cols; 4x STS.64
        float* Ad = Asm + s * ASTG + arow * ASTRIDE + ahalf * 2;
        float av0[4] = {pa0.x, pa0.y, pa0.z, pa0.w};
        float av1[4] = {pa1.x, pa1.y, pa1.z, pa1.w};
#pragma unroll
        for (int t = 0; t < 4; t++)
            *(float2*)(Ad + t * 4) = make_float2(av0[t], av1[t]);
        float* Bd = Bsm + s * BSTG + tid;
#pragma unroll
        for (int k = 0; k < 16; k++)
            Bd[k * BSTRIDE] = pb[k];
    };

    float acc[4][8][4];
#pragma unroll
    for (int i = 0; i < 4; i++)
#pragma unroll
        for (int j = 0; j < 8; j++)
#pragma unroll
            for (int r = 0; r < 4; r++) acc[i][j][r] = 0.f;

    loadA(0); loadB(0); storeAB(0);
    __syncthreads();

    int kq = lane & 3, g4 = lane >> 2;
    for (int c = 0; c < NCHUNK; c++) {
        int s = c & 1;
        if (c + 1 < NCHUNK) { loadA(c + 1); loadB(c + 1); }
        const float* Ab = Asm + s * ASTG;
        const float* Bb = Bsm + s * BSTG;
        // A fragments for whole chunk: 8x LDS.128
        float4 alo[4], ahi[4];
#pragma unroll
        for (int i = 0; i < 4; i++) {
            int m = wm + i * 16 + g4;
            alo[i] = *(const float4*)(Ab + m * ASTRIDE + kq * 4);
            ahi[i] = *(const float4*)(Ab + (m + 8) * ASTRIDE + kq * 4);
        }
#pragma unroll
        for (int kk = 0; kk < 2; kk++) {
            uint32_t bf[8][2];
#pragma unroll
            for (int j = 0; j < 8; j++) {
                int n = wn + j * 8 + g4;
                bf[j][0] = __float_as_uint(Bb[(kq + kk * 8) * BSTRIDE + n]);
                bf[j][1] = __float_as_uint(Bb[(kq + 4 + kk * 8) * BSTRIDE + n]);
            }
#pragma unroll
            for (int i = 0; i < 4; i++) {
                uint32_t af[4];
                if (kk == 0) {
                    af[0] = __float_as_uint(alo[i].x); af[1] = __float_as_uint(ahi[i].x);
                    af[2] = __float_as_uint(alo[i].y); af[3] = __float_as_uint(ahi[i].y);
                } else {
                    af[0] = __float_as_uint(alo[i].z); af[1] = __float_as_uint(ahi[i].z);
                    af[2] = __float_as_uint(alo[i].w); af[3] = __float_as_uint(ahi[i].w);
                }
#pragma unroll
                for (int j = 0; j < 8; j++)
                    mma1688(acc[i][j], af, bf[j]);
            }
        }
        if (c + 1 < NCHUNK) storeAB(s ^ 1);
        __syncthreads();
    }

#pragma unroll
    for (int i = 0; i < 4; i++) {
#pragma unroll
        for (int hh = 0; hh < 2; hh++) {
            int row = oc0 + wm + i * 16 + g4 + hh * 8;
            float inv = __ldg(q0 + row) * rsqrtf(__ldg(q3 + row) + 1e-5f);
            float add = __ldg(q1 + row) - __ldg(q2 + row) * inv;
#pragma unroll
            for (int j = 0; j < 8; j++) {
                int col = px0 + wn + j * 8 + kq * 2;
                size_t off = (size_t)row * NPIX + col;
                float v0 = fmaxf(acc[i][j][hh * 2 + 0] * inv + add, 0.f);
                float v1 = fmaxf(acc[i][j][hh * 2 + 1] * inv + add, 0.f);
                if (ROUND) { v0 = tf32r(v0); v1 = tf32r(v1); }
                *(float2*)(outp + off) = make_float2(v0, v1);
            }
        }
    }
}

// ---------------- final fused: out = W2*bott1 + b2 + att'*xr + x ----------------
__global__ void __launch_bounds__(256, 1) final_tc(
    const float* __restrict__ xexact, const float* __restrict__ b2,
    float* __restrict__ outp)
{
    extern __shared__ float dsm[];
    float* Asm = dsm;
    float* Bsm = dsm + 2 * ASTG;

    int tid = threadIdx.x, lane = tid & 31, wid = tid >> 5;
    int wm = (wid & 1) * 64, wn = (wid >> 1) * 64;
    int px0 = blockIdx.x * 256;
    int oc0 = blockIdx.y * 128;
    int b = blockIdx.z;
    const float* B1 = g_bott1 + (size_t)b * Cc * NPIX;
    const float* B2 = g_xr + (size_t)b * Cc * NPIX;
    const float* A2 = g_energy + (size_t)b * Cc * Cc;
    const float* xb = xexact + (size_t)b * Cc * NPIX;
    outp += (size_t)b * Cc * NPIX;

    int arow = tid >> 1, ahalf = tid & 1;
    int px = px0 + tid;

    float4 pa0, pa1;
    float pb[16];
    auto loadA = [&](int c) {
        int p = c >> 5;
        int ic = (c & 31) * 16;
        const float* base = p ? A2 : g_w2r;
        const float* ap = base + (size_t)(oc0 + arow) * Cc + ic + ahalf * 8;
        pa0 = *(const float4*)ap;
        pa1 = *(const float4*)(ap + 4);
    };
    auto loadB = [&](int c) {
        int p = c >> 5;
        int ic = (c & 31) * 16;
        const float* src = p ? B2 : B1;
#pragma unroll
        for (int k = 0; k < 16; k++)
            pb[k] = __ldg(src + (size_t)(ic + k) * NPIX + px);
    };
    auto storeAB = [&](int s) {
        float* Ad = Asm + s * ASTG + arow * ASTRIDE + ahalf * 2;
        float av0[4] = {pa0.x, pa0.y, pa0.z, pa0.w};
        float av1[4] = {pa1.x, pa1.y, pa1.z, pa1.w};
#pragma unroll
        for (int t = 0; t < 4; t++)
            *(float2*)(Ad + t * 4) = make_float2(av0[t], av1[t]);
        float* Bd = Bsm + s * BSTG + tid;
#pragma unroll
        for (int k = 0; k < 16; k++)
            Bd[k * BSTRIDE] = pb[k];
    };

    float acc[4][8][4];
#pragma unroll
    for (int i = 0; i < 4; i++)
#pragma unroll
        for (int j = 0; j < 8; j++)
#pragma unroll
            for (int r = 0; r < 4; r++) acc[i][j][r] = 0.f;

    loadA(0); loadB(0); storeAB(0);
    __syncthreads();

    int kq = lane & 3, g4 = lane >> 2;
    const int NCHUNK = 64;
    for (int c = 0; c < NCHUNK; c++) {
        int s = c & 1;
        if (c + 1 < NCHUNK) { loadA(c + 1); loadB(c + 1); }
        const float* Ab = Asm + s * ASTG;
        const float* Bb = Bsm + s * BSTG;
        float4 alo[4], ahi[4];
#pragma unroll
        for (int i = 0; i < 4; i++) {
            int m = wm + i * 16 + g4;
            alo[i] = *(const float4*)(Ab + m * ASTRIDE + kq * 4);
            ahi[i] = *(const float4*)(Ab + (m + 8) * ASTRIDE + kq * 4);
        }
#pragma unroll
        for (int kk = 0; kk < 2; kk++) {
            uint32_t bf[8][2];
#pragma unroll
            for (int j = 0; j < 8; j++) {
                int n = wn + j * 8 + g4;
                bf[j][0] = __float_as_uint(Bb[(kq + kk * 8) * BSTRIDE + n]);
                bf[j][1] = __float_as_uint(Bb[(kq + 4 + kk * 8) * BSTRIDE + n]);
            }
#pragma unroll
            for (int i = 0; i < 4; i++) {
                uint32_t af[4];
                if (kk == 0) {
                    af[0] = __float_as_uint(alo[i].x); af[1] = __float_as_uint(ahi[i].x);
                    af[2] = __float_as_uint(alo[i].y); af[3] = __float_as_uint(ahi[i].y);
                } else {
                    af[0] = __float_as_uint(alo[i].z); af[1] = __float_as_uint(ahi[i].z);
                    af[2] = __float_as_uint(alo[i].w); af[3] = __float_as_uint(ahi[i].w);
                }
#pragma unroll
                for (int j = 0; j < 8; j++)
                    mma1688(acc[i][j], af, bf[j]);
            }
        }
        if (c + 1 < NCHUNK) storeAB(s ^ 1);
        __syncthreads();
    }

#pragma unroll
    for (int i = 0; i < 4; i++) {
#pragma unroll
        for (int hh = 0; hh < 2; hh++) {
            int row = oc0 + wm + i * 16 + g4 + hh * 8;
            float add = __ldg(b2 + row);
#pragma unroll
            for (int j = 0; j < 8; j++) {
                int col = px0 + wn + j * 8 + kq * 2;
                size_t off = (size_t)row * NPIX + col;
                float2 xv = *(const float2*)(xb + off);
                *(float2*)(outp + off) = make_float2(
                    acc[i][j][hh * 2 + 0] + add + xv.x,
                    acc[i][j][hh * 2 + 1] + add + xv.y);
            }
        }
    }
}

// ---------------- CAM energy: 3xTF32 tensor-core, split-K ----------------
__global__ void __launch_bounds__(256, 2) egemm_tc()
{
    __shared__ float Ah[128][20], Al[128][20], Bh[128][20], Bl[128][20];

    int bz = blockIdx.z;
    int b = bz / ESPLIT, ks = bz - b * ESPLIT;
    const float* xh = g_xr + (size_t)b * Cc * NPIX;
    const float* xl = g_xlo + (size_t)b * Cc * NPIX;
    float* Cm = g_epart + (size_t)(ks * Bq + b) * Cc * Cc;
    const int KCH = NPIX / ESPLIT;
    int k0s = ks * KCH, k0e = k0s + KCH;

    int tid = threadIdx.x, lane = tid & 31, wid = tid >> 5;
    int wm = (wid & 1) * 64, wn = (wid >> 1) * 32;
    int row0 = blockIdx.y * 128, col0 = blockIdx.x * 128;
    int ar = tid >> 1, ak = (tid & 1) * 8;
    const float* Arh = xh + (size_t)(row0 + ar) * NPIX + ak;
    const float* Arl = xl + (size_t)(row0 + ar) * NPIX + ak;
    const float* Brh = xh + (size_t)(col0 + ar) * NPIX + ak;
    const float* Brl = xl + (size_t)(col0 + ar) * NPIX + ak;

    float acc[4][4][4];
#pragma unroll
    for (int i = 0; i < 4; i++)
#pragma unroll
        for (int j = 0; j < 4; j++)
#pragma unroll
            for (int r = 0; r < 4; r++) acc[i][j][r] = 0.f;

    for (int k0 = k0s; k0 < k0e; k0 += 16) {
        __syncthreads();
        *(float4*)&Ah[ar][ak]     = *(const float4*)(Arh + k0);
        *(float4*)&Ah[ar][ak + 4] = *(const float4*)(Arh + k0 + 4);
        *(float4*)&Al[ar][ak]     = *(const float4*)(Arl + k0);
        *(float4*)&Al[ar][ak + 4] = *(const float4*)(Arl + k0 + 4);
        *(float4*)&Bh[ar][ak]     = *(const float4*)(Brh + k0);
        *(float4*)&Bh[ar][ak + 4] = *(const float4*)(Brh + k0 + 4);
        *(float4*)&Bl[ar][ak]     = *(const float4*)(Brl + k0);
        *(float4*)&Bl[ar][ak + 4] = *(const float4*)(Brl + k0 + 4);
        __syncthreads();
#pragma unroll
        for (int kk = 0; kk < 16; kk += 8) {
            int kq = kk + (lane & 3);
            int g4 = lane >> 2;
            uint32_t ah[4][4], al[4][4];
#pragma unroll
            for (int i = 0; i < 4; i++) {
                int m = wm + i * 16 + g4;
                ah[i][0] = __float_as_uint(Ah[m][kq]);
                ah[i][1] = __float_as_uint(Ah[m + 8][kq]);
                ah[i][2] = __float_as_uint(Ah[m][kq + 4]);
                ah[i][3] = __float_as_uint(Ah[m + 8][kq + 4]);
                al[i][0] = __float_as_uint(Al[m][kq]);
                al[i][1] = __float_as_uint(Al[m + 8][kq]);
                al[i][2] = __float_as_uint(Al[m][kq + 4]);
                al[i][3] = __float_as_uint(Al[m + 8][kq + 4]);
            }
#pragma unroll
            for (int j = 0; j < 4; j++) {
                int n = wn + j * 8 + g4;
                uint32_t bh[2], bl[2];
                bh[0] = __float_as_uint(Bh[n][kq]);
                bh[1] = __float_as_uint(Bh[n][kq + 4]);
                bl[0] = __float_as_uint(Bl[n][kq]);
                bl[1] = __float_as_uint(Bl[n][kq + 4]);
#pragma unroll
                for (int i = 0; i < 4; i++) {
                    mma1688(acc[i][j], ah[i], bh);
                    mma1688(acc[i][j], ah[i], bl);
                    mma1688(acc[i][j], al[i], bh);
                }
            }
        }
    }

#pragma unroll
    for (int i = 0; i < 4; i++) {
#pragma unroll
        for (int hh = 0; hh < 2; hh++) {
            int row = row0 + wm + i * 16 + (lane >> 2) + hh * 8;
#pragma unroll
            for (int j = 0; j < 4; j++) {
                int col = col0 + wn + j * 8 + (lane & 3) * 2;
                *(float2*)&Cm[(size_t)row * Cc + col] = make_float2(
                    acc[i][j][hh * 2 + 0], acc[i][j][hh * 2 + 1]);
            }
        }
    }
}

// ---------------- q/k/v 1x1 convs ----------------
__global__ void __launch_bounds__(128) qkv_kernel(
    const float* __restrict__ wq, const float* __restrict__ bq,
    const float* __restrict__ wk, const float* __restrict__ bk,
    const float* __restrict__ wv, const float* __restrict__ bv)
{
    int b = blockIdx.y;
    int px0 = blockIdx.x * 64;
    int t = threadIdx.x;
    int px = t & 63;
    int half = t >> 6;
    __shared__ float xs[128][64];
    for (int idx = t; idx < 128 * 64; idx += 128) {
        int ic = idx >> 6, p = idx & 63;
        xs[ic][p] = g_out1[((size_t)b * ICd + ic) * NPIX + px0 + p];
    }
    __syncthreads();
    for (int oc = half * 80; oc < half * 80 + 80; oc++) {
        const float* wrow; float bias; float* dst;
        if (oc < 16) { wrow = wq + oc * 128; bias = bq[oc];
                       dst = g_q + ((size_t)b * QCd + oc) * NPIX; }
        else if (oc < 32) { int o = oc - 16; wrow = wk + o * 128; bias = bk[o];
                            dst = g_k + ((size_t)b * QCd + o) * NPIX; }
        else { int o = oc - 32; wrow = wv + o * 128; bias = bv[o];
               dst = g_v + ((size_t)b * ICd + o) * NPIX; }
        float a = bias;
#pragma unroll 8
        for (int ic = 0; ic < 128; ic += 4) {
            float4 w4 = *(const float4*)(wrow + ic);
            a += w4.x * xs[ic][px] + w4.y * xs[ic + 1][px]
               + w4.z * xs[ic + 2][px] + w4.w * xs[ic + 3][px];
        }
        dst[px0 + px] = a;
    }
}

// ---------------- criss-cross attention ----------------
__global__ void __launch_bounds__(192) cca2_kernel(const float* __restrict__ gamma)
{
    extern __shared__ float sm[];
    float* e = sm;
    float* qs = sm + 192 * 96;
    float* ks_ = qs + 16 * 96;
    float* vr = ks_ + 16 * 96;

    int h = blockIdx.x, b = blockIdx.y;
    int tid = threadIdx.x;
    const float* qb = g_q + (size_t)b * QCd * NPIX;
    const float* kb = g_k + (size_t)b * QCd * NPIX;
    const float* vb = g_v + (size_t)b * ICd * NPIX;

    for (int idx = tid; idx < 16 * 96; idx += 192) {
        int c = idx / 96, w = idx - c * 96;
        qs[c * 96 + w] = qb[c * NPIX + h * Wd + w];
        ks_[c * 96 + w] = kb[c * NPIX + h * Wd + w];
    }
    __syncthreads();
    for (int idx = tid; idx < 96 * 96; idx += 192) {
        int s = idx / 96, w = idx - s * 96;
        float a = 0.f;
#pragma unroll
        for (int c = 0; c < 16; c++) a += qs[c * 96 + w] * ks_[c * 96 + s];
        e[(96 + s) * 96 + w] = a;
    }
    for (int idx = tid; idx < 96 * 96; idx += 192) {
        int s = idx / 96, w = idx - s * 96;
        float a = 0.f;
#pragma unroll
        for (int c = 0; c < 16; c++) a += qs[c * 96 + w] * kb[c * NPIX + s * Wd + w];
        e[s * 96 + w] = (s == h) ? -1e30f : a;
    }
    __syncthreads();
    if (tid < 96) {
        int w = tid;
        float M = -1e30f;
        for (int i = 0; i < 192; i++) M = fmaxf(M, e[i * 96 + w]);
        float S = 0.f;
        for (int i = 0; i < 192; i++) {
            float p = __expf(e[i * 96 + w] - M);
            e[i * 96 + w] = p; S += p;
        }
        float inv = 1.f / S;
        for (int i = 0; i < 192; i++) e[i * 96 + w] *= inv;
    }
    __syncthreads();
    int g = tid / 96;
    int w = tid - g * 96;
    float gam = __ldg(gamma);
    for (int cc = 0; cc < 64; cc++) {
        int c = g * 64 + cc;
        vr[g * 96 + w] = vb[(size_t)c * NPIX + h * Wd + w];
        __syncthreads();
        float oH = 0.f, oW = 0.f;
        const float* vcol = vb + (size_t)c * NPIX + w;
#pragma unroll 4
        for (int s = 0; s < 96; s++) {
            oH += vcol[s * Wd] * e[s * 96 + w];
            oW += vr[g * 96 + s] * e[(96 + s) * 96 + w];
        }
        size_t o = ((size_t)b * ICd + c) * NPIX + h * Wd + w;
        g_cca[o] = tf32r(gam * (oH + oW) + g_out1[o]);
        __syncthreads();
    }
}

// ---------------- CAM softmax (sums partials, scales by gamma_cam) ----------------
__global__ void __launch_bounds__(128) cam_softmax_kernel(const float* __restrict__ gma)
{
    int b = blockIdx.y, c = blockIdx.x;
    int t = threadIdx.x;
    __shared__ float red[4];
    float4 v = make_float4(0.f, 0.f, 0.f, 0.f);
#pragma unroll
    for (int s = 0; s < ESPLIT; s++) {
        const float4 p = *(const float4*)&g_epart[(((size_t)(s * Bq + b)) * Cc + c) * Cc + t * 4];
        v.x += p.x; v.y += p.y; v.z += p.z; v.w += p.w;
    }
    float lmn = fminf(fminf(v.x, v.y), fminf(v.z, v.w));
#pragma unroll
    for (int o = 16; o; o >>= 1) lmn = fminf(lmn, __shfl_xor_sync(0xffffffffu, lmn, o));
    if ((t & 31) == 0) red[t >> 5] = lmn;
    __syncthreads();
    float mn = fminf(fminf(red[0], red[1]), fminf(red[2], red[3]));
    __syncthreads();
    float4 p;
    p.x = __expf(mn - v.x); p.y = __expf(mn - v.y);
    p.z = __expf(mn - v.z); p.w = __expf(mn - v.w);
    float ls = p.x + p.y + p.z + p.w;
#pragma unroll
    for (int o = 16; o; o >>= 1) ls += __shfl_xor_sync(0xffffffffu, ls, o);
    if ((t & 31) == 0) red[t >> 5] = ls;
    __syncthreads();
    float gam = __ldg(gma);
    float inv = gam / (red[0] + red[1] + red[2] + red[3]);
    p.x = tf32r(p.x * inv); p.y = tf32r(p.y * inv);
    p.z = tf32r(p.z * inv); p.w = tf32r(p.w * inv);
    *(float4*)&g_energy[((size_t)b * Cc + c) * Cc + t * 4] = p;
}

// ---------------- launch ----------------
extern "C" void kernel_launch(void* const* d_in, const int* in_sizes, int n_in,
                              void* d_out, int out_size)
{
    const float* x        = (const float*)d_in[0];
    const float* conva_w  = (const float*)d_in[1];
    const float* bn1_s    = (const float*)d_in[2];
    const float* bn1_b    = (const float*)d_in[3];
    const float* bn1_m    = (const float*)d_in[4];
    const float* bn1_v    = (const float*)d_in[5];
    const float* wq       = (const float*)d_in[6];
    const float* bq       = (const float*)d_in[7];
    const float* wk       = (const float*)d_in[8];
    const float* bk       = (const float*)d_in[9];
    const float* wv       = (const float*)d_in[10];
    const float* bv       = (const float*)d_in[11];
    const float* gamma_cca= (const float*)d_in[12];
    const float* convb_w  = (const float*)d_in[13];
    const float* bn2_s    = (const float*)d_in[14];
    const float* bn2_b    = (const float*)d_in[15];
    const float* bn2_m    = (const float*)d_in[16];
    const float* bn2_v    = (const float*)d_in[17];
    const float* bot_w1   = (const float*)d_in[18];
    const float* bn3_s    = (const float*)d_in[19];
    const float* bn3_b    = (const float*)d_in[20];
    const float* bn3_m    = (const float*)d_in[21];
    const float* bn3_v    = (const float*)d_in[22];
    const float* bot_w2   = (const float*)d_in[23];
    const float* bot_b2   = (const float*)d_in[24];
    const float* gamma_cam= (const float*)d_in[25];
    float* out = (float*)d_out;

    float *p_xr, *p_xlo, *p_cca, *p_b1, *p_wta, *p_wtb, *p_wt1, *p_out1, *p_out2;
    cudaGetSymbolAddress((void**)&p_xr, g_xr);
    cudaGetSymbolAddress((void**)&p_xlo, g_xlo);
    cudaGetSymbolAddress((void**)&p_cca, g_cca);
    cudaGetSymbolAddress((void**)&p_b1, g_bott1);
    cudaGetSymbolAddress((void**)&p_wta, g_wta);
    cudaGetSymbolAddress((void**)&p_wtb, g_wtb);
    cudaGetSymbolAddress((void**)&p_wt1, g_wt1);
    cudaGetSymbolAddress((void**)&p_out1, g_out1);
    cudaGetSymbolAddress((void**)&p_out2, g_out2);

    cudaFuncSetAttribute(cca2_kernel, cudaFuncAttributeMaxDynamicSharedMemorySize, 90112);
    cudaFuncSetAttribute(conv_tc<9, true>, cudaFuncAttributeMaxDynamicSharedMemorySize, CONV_SMEM);
    cudaFuncSetAttribute(final_tc, cudaFuncAttributeMaxDynamicSharedMemorySize, CONV_SMEM);

    // prep (2 launches so conv kernels land at ncu -s 5)
    splitcopy4<<<512, 256>>>(x, p_xr, p_xlo, Bq * Cc * NPIX / 4);
    prep_weights<<<512, 256>>>(conva_w, convb_w, bot_w1, bot_w2);

    // conva 512->128 (+bn1+relu, rounded)
    conv_tc<9, true><<<dim3(36, 1, Bq), 256, CONV_SMEM>>>(
        p_xr, Cc, nullptr, 0, p_wta, ICd, p_out1,
        bn1_s, bn1_b, bn1_m, bn1_v);

    // qkv
    qkv_kernel<<<dim3(NPIX / 64, Bq), 128>>>(wq, bq, wk, bk, wv, bv);

    // cca
    cca2_kernel<<<dim3(Hd, Bq), 192, 90112>>>(gamma_cca);

    // convb 128->128 (+bn2+relu, rounded)   <- ncu launch index 5
    conv_tc<9, true><<<dim3(36, 1, Bq), 256, CONV_SMEM>>>(
        p_cca, ICd, nullptr, 0, p_wtb, ICd, p_out2,
        bn2_s, bn2_b, bn2_m, bn2_v);

    // bot conv1 concat(x,out2) 640->512 (+bn3+relu, rounded)
    conv_tc<9, true><<<dim3(36, 4, Bq), 256, CONV_SMEM>>>(
        p_xr, Cc, p_out2, ICd, p_wt1, Cc, p_b1,
        bn3_s, bn3_b, bn3_m, bn3_v);

    // CAM energy (3xTF32 TC, split-K)
    egemm_tc<<<dim3(Cc / 128, Cc / 128, Bq * ESPLIT), 256>>>();

    // CAM softmax -> g_energy (gamma-scaled attention)
    cam_softmax_kernel<<<dim3(Cc, Bq), 128>>>(gamma_cam);

    // final fused: out = W2*bott1 + b2 + att'*xr + x
    final_tc<<<dim3(36, 4, Bq), 256, CONV_SMEM>>>(x, bot_b2, out);
}

// round 9
// speedup vs baseline: 3.8511x; 1.0104x over previous
#include <cuda_runtime.h>
#include <cstdint>

#define Bq 4
#define Cc 512
#define NPIX 9216
#define ICd 128
#define Hd 96
#define Wd 96
#define ESPLIT 4

// ---------------- scratch ----------------
__device__ float g_xr[(size_t)Bq * Cc * NPIX];    // tf32-rounded x
__device__ float g_out1[Bq * ICd * NPIX];
__device__ float g_qkv[(size_t)Bq * 192 * NPIX];  // rows: 0-15 q, 16-31 k, 32-159 v
__device__ float g_cca[Bq * ICd * NPIX];
__device__ float g_out2[Bq * ICd * NPIX];
__device__ float g_bott1[(size_t)Bq * Cc * NPIX];
__device__ float g_energy[Bq * Cc * Cc];
__device__ float g_epart[(size_t)ESPLIT * Bq * Cc * Cc];
__device__ float g_wta[9 * 128 * 512];
__device__ float g_wtb[9 * 128 * 128];
__device__ float g_wt1[9 * 512 * 640];
__device__ float g_w2r[512 * 512];
__device__ float g_wqkv[192 * 128];
__device__ float g_bqkv[192];

__device__ __forceinline__ float tf32r(float x) {
    uint32_t u;
    asm("cvt.rna.tf32.f32 %0, %1;" : "=r"(u) : "f"(x));
    return __uint_as_float(u);
}

__device__ __forceinline__ void mma1688(float* c, const uint32_t* a, const uint32_t* b) {
    asm volatile(
        "mma.sync.aligned.m16n8k8.row.col.f32.tf32.tf32.f32 "
        "{%0,%1,%2,%3}, {%4,%5,%6,%7}, {%8,%9}, {%0,%1,%2,%3};"
        : "+f"(c[0]), "+f"(c[1]), "+f"(c[2]), "+f"(c[3])
        : "r"(a[0]), "r"(a[1]), "r"(a[2]), "r"(a[3]), "r"(b[0]), "r"(b[1]));
}

#define CPA4(dst, src, sz) \
    asm volatile("cp.async.ca.shared.global [%0], [%1], 4, %2;" :: "r"(dst), "l"(src), "r"(sz))
#define CP_COMMIT() asm volatile("cp.async.commit_group;" ::: "memory")
#define CP_WAIT0()  asm volatile("cp.async.wait_group 0;" ::: "memory")

// ---------------- prep ----------------
__global__ void roundcopy4(const float* __restrict__ s, float* __restrict__ d, int n4) {
    for (int i = blockIdx.x * blockDim.x + threadIdx.x; i < n4; i += gridDim.x * blockDim.x) {
        float4 v = ((const float4*)s)[i];
        v.x = tf32r(v.x); v.y = tf32r(v.y); v.z = tf32r(v.z); v.w = tf32r(v.w);
        ((float4*)d)[i] = v;
    }
}

__global__ void prep_weights(const float* __restrict__ wa, const float* __restrict__ wb,
                             const float* __restrict__ w1, const float* __restrict__ w2,
                             const float* __restrict__ wq, const float* __restrict__ bq,
                             const float* __restrict__ wk, const float* __restrict__ bk,
                             const float* __restrict__ wv, const float* __restrict__ bv)
{
    const int n1 = 128 * 512 * 9;
    const int n2 = 128 * 128 * 9;
    const int n3 = 512 * 640 * 9;
    const int n4 = 512 * 512;
    const int n5 = 192 * 128;
    const int ntot = n1 + n2 + n3 + n4 + n5 + 192;
    for (int i = blockIdx.x * blockDim.x + threadIdx.x; i < ntot; i += gridDim.x * blockDim.x) {
        if (i < n1) {
            int oc = i / (512 * 9);
            int rem = i - oc * (512 * 9);
            int ic = rem / 9, tap = rem - ic * 9;
            g_wta[((size_t)tap * 128 + oc) * 512 + ic] = tf32r(wa[i]);
        } else if (i < n1 + n2) {
            int j = i - n1;
            int oc = j / (128 * 9);
            int rem = j - oc * (128 * 9);
            int ic = rem / 9, tap = rem - ic * 9;
            g_wtb[((size_t)tap * 128 + oc) * 128 + ic] = tf32r(wb[j]);
        } else if (i < n1 + n2 + n3) {
            int j = i - n1 - n2;
            int oc = j / (640 * 9);
            int rem = j - oc * (640 * 9);
            int ic = rem / 9, tap = rem - ic * 9;
            g_wt1[((size_t)tap * 512 + oc) * 640 + ic] = tf32r(w1[j]);
        } else if (i < n1 + n2 + n3 + n4) {
            int j = i - n1 - n2 - n3;
            g_w2r[j] = tf32r(w2[j]);
        } else if (i < n1 + n2 + n3 + n4 + n5) {
            int j = i - n1 - n2 - n3 - n4;
            int r = j >> 7, ic = j & 127;
            float v = 0.f;
            if (r < 16) v = wq[r * 128 + ic];
            else if (r < 32) v = wk[(r - 16) * 128 + ic];
            else if (r < 160) v = wv[(r - 32) * 128 + ic];
            g_wqkv[j] = tf32r(v);
        } else {
            int r = i - n1 - n2 - n3 - n4 - n5;
            float v = 0.f;
            if (r < 16) v = bq[r];
            else if (r < 32) v = bk[r - 16];
            else if (r < 160) v = bv[r - 32];
            g_bqkv[r] = v;
        }
    }
}

// ---------------- tf32 TC implicit-GEMM conv (+BN+ReLU) ----------------
// CTA: 128 oc x 256 px, BK=16, 8 warps of 64x64. A perm-K layout; B via cp.async.
#define ASTRIDE 20
#define ASTG (128 * ASTRIDE)
#define BSTRIDE 260
#define BSTG (16 * BSTRIDE)
#define CONV_SMEM ((2 * ASTG + 2 * BSTG) * 4)

template<int NTAPS, bool ROUND>
__global__ void __launch_bounds__(256, 1) conv_tc(
    const float* __restrict__ in1, int cin1,
    const float* __restrict__ in2, int cin2,
    const float* __restrict__ Aw, int OCtot,
    float* __restrict__ outp,
    const float* __restrict__ q0, const float* __restrict__ q1,
    const float* __restrict__ q2, const float* __restrict__ q3)
{
    const int CIN = cin1 + cin2;
    const int NCHUNK = (NTAPS * CIN) / 16;

    extern __shared__ float dsm[];
    float* Asm = dsm;
    float* Bsm = dsm + 2 * ASTG;
    uint32_t bsmu = (uint32_t)__cvta_generic_to_shared(Bsm);

    int tid = threadIdx.x, lane = tid & 31, wid = tid >> 5;
    int wm = (wid & 1) * 64, wn = (wid >> 1) * 64;
    int px0 = blockIdx.x * 256;
    int oc0 = blockIdx.y * 128;
    int b = blockIdx.z;
    in1 += (size_t)b * cin1 * NPIX;
    if (cin2 > 0) in2 += (size_t)b * cin2 * NPIX;
    outp += (size_t)b * OCtot * NPIX;

    int arow = tid >> 1, ahalf = tid & 1;
    int px = px0 + tid;
    int ph = px / 96, pw = px - ph * 96;

    float4 pa0, pa1;

    auto loadA = [&](int c) {
        int ko = c * 16;
        int tap = (NTAPS == 9) ? ko / CIN : 0;
        int ic = ko - tap * CIN;
        const float* ap = Aw + ((size_t)tap * OCtot + oc0 + arow) * CIN + ic + ahalf * 8;
        pa0 = *(const float4*)ap;
        pa1 = *(const float4*)(ap + 4);
    };
    auto storeA = [&](int s) {
        float* Ad = Asm + s * ASTG + arow * ASTRIDE + ahalf * 2;
        float av0[4] = {pa0.x, pa0.y, pa0.z, pa0.w};
        float av1[4] = {pa1.x, pa1.y, pa1.z, pa1.w};
#pragma unroll
        for (int t = 0; t < 4; t++)
            *(float2*)(Ad + t * 4) = make_float2(av0[t], av1[t]);
    };
    auto issueB = [&](int c, int s) {
        int ko = c * 16;
        int tap = (NTAPS == 9) ? ko / CIN : 0;
        int ic = ko - tap * CIN;
        const float* src = (ic < cin1) ? (in1 + (size_t)ic * NPIX)
                                       : (in2 + (size_t)(ic - cin1) * NPIX);
        const float* sp;
        uint32_t sz = 4;
        if (NTAPS == 9) {
            int dh = tap / 3 - 1, dw = tap % 3 - 1;
            int hh = ph + dh, ww = pw + dw;
            bool ok = ((unsigned)hh < 96u) && ((unsigned)ww < 96u);
            sz = ok ? 4u : 0u;
            sp = src + px + dh * 96 + dw;
        } else {
            sp = src + px;
        }
        uint32_t bd = bsmu + (uint32_t)((s * BSTG + tid) * 4);
#pragma unroll
        for (int k = 0; k < 16; k++)
            CPA4(bd + k * (BSTRIDE * 4), sp + (size_t)k * NPIX, sz);
        CP_COMMIT();
    };

    float acc[4][8][4];
#pragma unroll
    for (int i = 0; i < 4; i++)
#pragma unroll
        for (int j = 0; j < 8; j++)
#pragma unroll
            for (int r = 0; r < 4; r++) acc[i][j][r] = 0.f;

    loadA(0);
    issueB(0, 0);
    storeA(0);
    CP_WAIT0();
    __syncthreads();

    int kq = lane & 3, g4 = lane >> 2;
    for (int c = 0; c < NCHUNK; c++) {
        int s = c & 1;
        if (c + 1 < NCHUNK) { loadA(c + 1); issueB(c + 1, s ^ 1); }
        const float* Ab = Asm + s * ASTG;
        const float* Bb = Bsm + s * BSTG;
        float4 alo[4], ahi[4];
#pragma unroll
        for (int i = 0; i < 4; i++) {
            int m = wm + i * 16 + g4;
            alo[i] = *(const float4*)(Ab + m * ASTRIDE + kq * 4);
            ahi[i] = *(const float4*)(Ab + (m + 8) * ASTRIDE + kq * 4);
        }
#pragma unroll
        for (int kk = 0; kk < 2; kk++) {
            uint32_t bf[8][2];
#pragma unroll
            for (int j = 0; j < 8; j++) {
                int n = wn + j * 8 + g4;
                bf[j][0] = __float_as_uint(Bb[(kq + kk * 8) * BSTRIDE + n]);
                bf[j][1] = __float_as_uint(Bb[(kq + 4 + kk * 8) * BSTRIDE + n]);
            }
#pragma unroll
            for (int i = 0; i < 4; i++) {
                uint32_t af[4];
                if (kk == 0) {
                    af[0] = __float_as_uint(alo[i].x); af[1] = __float_as_uint(ahi[i].x);
                    af[2] = __float_as_uint(alo[i].y); af[3] = __float_as_uint(ahi[i].y);
                } else {
                    af[0] = __float_as_uint(alo[i].z); af[1] = __float_as_uint(ahi[i].z);
                    af[2] = __float_as_uint(alo[i].w); af[3] = __float_as_uint(ahi[i].w);
                }
#pragma unroll
                for (int j = 0; j < 8; j++)
                    mma1688(acc[i][j], af, bf[j]);
            }
        }
        if (c + 1 < NCHUNK) { storeA(s ^ 1); CP_WAIT0(); }
        __syncthreads();
    }

#pragma unroll
    for (int i = 0; i < 4; i++) {
#pragma unroll
        for (int hh = 0; hh < 2; hh++) {
            int row = oc0 + wm + i * 16 + g4 + hh * 8;
            float inv = __ldg(q0 + row) * rsqrtf(__ldg(q3 + row) + 1e-5f);
            float add = __ldg(q1 + row) - __ldg(q2 + row) * inv;
#pragma unroll
            for (int j = 0; j < 8; j++) {
                int col = px0 + wn + j * 8 + kq * 2;
                size_t off = (size_t)row * NPIX + col;
                float v0 = fmaxf(acc[i][j][hh * 2 + 0] * inv + add, 0.f);
                float v1 = fmaxf(acc[i][j][hh * 2 + 1] * inv + add, 0.f);
                if (ROUND) { v0 = tf32r(v0); v1 = tf32r(v1); }
                *(float2*)(outp + off) = make_float2(v0, v1);
            }
        }
    }
}

// ---------------- qkv via TC: g_qkv[192][NPIX] = Wqkv[192][128] @ out1 + b ----------------
__global__ void __launch_bounds__(256, 1) qkv_tc()
{
    __shared__ float Asm[2][64 * ASTRIDE];
    __shared__ float Bsm[2][BSTG];
    uint32_t bsmu = (uint32_t)__cvta_generic_to_shared(&Bsm[0][0]);

    int tid = threadIdx.x, lane = tid & 31, wid = tid >> 5;
    int wn = wid * 32;
    int px0 = blockIdx.x * 256;
    int oc0 = blockIdx.y * 64;
    int b = blockIdx.z;
    const float* in = g_out1 + (size_t)b * ICd * NPIX;
    float* outp = g_qkv + (size_t)b * 192 * NPIX;

    int arow = tid >> 1, ahalf = tid & 1;
    int px = px0 + tid;

    float4 pa0, pa1;
    auto loadA = [&](int c) {
        if (tid < 128) {
            const float* ap = g_wqkv + (size_t)(oc0 + arow) * 128 + c * 16 + ahalf * 8;
            pa0 = *(const float4*)ap;
            pa1 = *(const float4*)(ap + 4);
        }
    };
    auto storeA = [&](int s) {
        if (tid < 128) {
            float* Ad = &Asm[s][arow * ASTRIDE + ahalf * 2];
            float av0[4] = {pa0.x, pa0.y, pa0.z, pa0.w};
            float av1[4] = {pa1.x, pa1.y, pa1.z, pa1.w};
#pragma unroll
            for (int t = 0; t < 4; t++)
                *(float2*)(Ad + t * 4) = make_float2(av0[t], av1[t]);
        }
    };
    auto issueB = [&](int c, int s) {
        const float* sp = in + (size_t)c * 16 * NPIX + px;
        uint32_t bd = bsmu + (uint32_t)((s * BSTG + tid) * 4);
#pragma unroll
        for (int k = 0; k < 16; k++)
            CPA4(bd + k * (BSTRIDE * 4), sp + (size_t)k * NPIX, 4u);
        CP_COMMIT();
    };

    float acc[4][4][4];
#pragma unroll
    for (int i = 0; i < 4; i++)
#pragma unroll
        for (int j = 0; j < 4; j++)
#pragma unroll
            for (int r = 0; r < 4; r++) acc[i][j][r] = 0.f;

    loadA(0); issueB(0, 0); storeA(0);
    CP_WAIT0();
    __syncthreads();

    int kq = lane & 3, g4 = lane >> 2;
    const int NCHUNK = 8;
    for (int c = 0; c < NCHUNK; c++) {
        int s = c & 1;
        if (c + 1 < NCHUNK) { loadA(c + 1); issueB(c + 1, s ^ 1); }
        const float* Ab = &Asm[s][0];
        const float* Bb = &Bsm[s][0];
        float4 alo[4], ahi[4];
#pragma unroll
        for (int i = 0; i < 4; i++) {
            int m = i * 16 + g4;
            alo[i] = *(const float4*)(Ab + m * ASTRIDE + kq * 4);
            ahi[i] = *(const float4*)(Ab + (m + 8) * ASTRIDE + kq * 4);
        }
#pragma unroll
        for (int kk = 0; kk < 2; kk++) {
            uint32_t bf[4][2];
#pragma unroll
            for (int j = 0; j < 4; j++) {
                int n = wn + j * 8 + g4;
                bf[j][0] = __float_as_uint(Bb[(kq + kk * 8) * BSTRIDE + n]);
                bf[j][1] = __float_as_uint(Bb[(kq + 4 + kk * 8) * BSTRIDE + n]);
            }
#pragma unroll
            for (int i = 0; i < 4; i++) {
                uint32_t af[4];
                if (kk == 0) {
                    af[0] = __float_as_uint(alo[i].x); af[1] = __float_as_uint(ahi[i].x);
                    af[2] = __float_as_uint(alo[i].y); af[3] = __float_as_uint(ahi[i].y);
                } else {
                    af[0] = __float_as_uint(alo[i].z); af[1] = __float_as_uint(ahi[i].z);
                    af[2] = __float_as_uint(alo[i].w); af[3] = __float_as_uint(ahi[i].w);
                }
#pragma unroll
                for (int j = 0; j < 4; j++)
                    mma1688(acc[i][j], af, bf[j]);
            }
        }
        if (c + 1 < NCHUNK) { storeA(s ^ 1); CP_WAIT0(); }
        __syncthreads();
    }

#pragma unroll
    for (int i = 0; i < 4; i++) {
#pragma unroll
        for (int hh = 0; hh < 2; hh++) {
            int row = oc0 + i * 16 + g4 + hh * 8;
            float add = g_bqkv[row];
#pragma unroll
            for (int j = 0; j < 4; j++) {
                int col = px0 + wn + j * 8 + kq * 2;
                *(float2*)(outp + (size_t)row * NPIX + col) = make_float2(
                    acc[i][j][hh * 2 + 0] + add, acc[i][j][hh * 2 + 1] + add);
            }
        }
    }
}

// ---------------- final fused: out = W2*bott1 + b2 + att'*xr + x ----------------
__global__ void __launch_bounds__(256, 1) final_tc(
    const float* __restrict__ xexact, const float* __restrict__ b2,
    float* __restrict__ outp)
{
    extern __shared__ float dsm[];
    float* Asm = dsm;
    float* Bsm = dsm + 2 * ASTG;
    uint32_t bsmu = (uint32_t)__cvta_generic_to_shared(Bsm);

    int tid = threadIdx.x, lane = tid & 31, wid = tid >> 5;
    int wm = (wid & 1) * 64, wn = (wid >> 1) * 64;
    int px0 = blockIdx.x * 256;
    int oc0 = blockIdx.y * 128;
    int b = blockIdx.z;
    const float* B1 = g_bott1 + (size_t)b * Cc * NPIX;
    const float* B2 = g_xr + (size_t)b * Cc * NPIX;
    const float* A2 = g_energy + (size_t)b * Cc * Cc;
    const float* xb = xexact + (size_t)b * Cc * NPIX;
    outp += (size_t)b * Cc * NPIX;

    int arow = tid >> 1, ahalf = tid & 1;
    int px = px0 + tid;

    float4 pa0, pa1;
    auto loadA = [&](int c) {
        int p = c >> 5;
        int ic = (c & 31) * 16;
        const float* base = p ? A2 : g_w2r;
        const float* ap = base + (size_t)(oc0 + arow) * Cc + ic + ahalf * 8;
        pa0 = *(const float4*)ap;
        pa1 = *(const float4*)(ap + 4);
    };
    auto storeA = [&](int s) {
        float* Ad = Asm + s * ASTG + arow * ASTRIDE + ahalf * 2;
        float av0[4] = {pa0.x, pa0.y, pa0.z, pa0.w};
        float av1[4] = {pa1.x, pa1.y, pa1.z, pa1.w};
#pragma unroll
        for (int t = 0; t < 4; t++)
            *(float2*)(Ad + t * 4) = make_float2(av0[t], av1[t]);
    };
    auto issueB = [&](int c, int s) {
        int p = c >> 5;
        int ic = (c & 31) * 16;
        const float* sp = (p ? B2 : B1) + (size_t)ic * NPIX + px;
        uint32_t bd = bsmu + (uint32_t)((s * BSTG + tid) * 4);
#pragma unroll
        for (int k = 0; k < 16; k++)
            CPA4(bd + k * (BSTRIDE * 4), sp + (size_t)k * NPIX, 4u);
        CP_COMMIT();
    };

    float acc[4][8][4];
#pragma unroll
    for (int i = 0; i < 4; i++)
#pragma unroll
        for (int j = 0; j < 8; j++)
#pragma unroll
            for (int r = 0; r < 4; r++) acc[i][j][r] = 0.f;

    loadA(0); issueB(0, 0); storeA(0);
    CP_WAIT0();
    __syncthreads();

    int kq = lane & 3, g4 = lane >> 2;
    const int NCHUNK = 64;
    for (int c = 0; c < NCHUNK; c++) {
        int s = c & 1;
        if (c + 1 < NCHUNK) { loadA(c + 1); issueB(c + 1, s ^ 1); }
        const float* Ab = Asm + s * ASTG;
        const float* Bb = Bsm + s * BSTG;
        float4 alo[4], ahi[4];
#pragma unroll
        for (int i = 0; i < 4; i++) {
            int m = wm + i * 16 + g4;
            alo[i] = *(const float4*)(Ab + m * ASTRIDE + kq * 4);
            ahi[i] = *(const float4*)(Ab + (m + 8) * ASTRIDE + kq * 4);
        }
#pragma unroll
        for (int kk = 0; kk < 2; kk++) {
            uint32_t bf[8][2];
#pragma unroll
            for (int j = 0; j < 8; j++) {
                int n = wn + j * 8 + g4;
                bf[j][0] = __float_as_uint(Bb[(kq + kk * 8) * BSTRIDE + n]);
                bf[j][1] = __float_as_uint(Bb[(kq + 4 + kk * 8) * BSTRIDE + n]);
            }
#pragma unroll
            for (int i = 0; i < 4; i++) {
                uint32_t af[4];
                if (kk == 0) {
                    af[0] = __float_as_uint(alo[i].x); af[1] = __float_as_uint(ahi[i].x);
                    af[2] = __float_as_uint(alo[i].y); af[3] = __float_as_uint(ahi[i].y);
                } else {
                    af[0] = __float_as_uint(alo[i].z); af[1] = __float_as_uint(ahi[i].z);
                    af[2] = __float_as_uint(alo[i].w); af[3] = __float_as_uint(ahi[i].w);
                }
#pragma unroll
                for (int j = 0; j < 8; j++)
                    mma1688(acc[i][j], af, bf[j]);
            }
        }
        if (c + 1 < NCHUNK) { storeA(s ^ 1); CP_WAIT0(); }
        __syncthreads();
    }

#pragma unroll
    for (int i = 0; i < 4; i++) {
#pragma unroll
        for (int hh = 0; hh < 2; hh++) {
            int row = oc0 + wm + i * 16 + g4 + hh * 8;
            float add = __ldg(b2 + row);
#pragma unroll
            for (int j = 0; j < 8; j++) {
                int col = px0 + wn + j * 8 + kq * 2;
                size_t off = (size_t)row * NPIX + col;
                float2 xv = *(const float2*)(xb + off);
                *(float2*)(outp + off) = make_float2(
                    acc[i][j][hh * 2 + 0] + add + xv.x,
                    acc[i][j][hh * 2 + 1] + add + xv.y);
            }
        }
    }
}

// ---------------- CAM energy: 3xTF32 TC, split-K, on-the-fly hi/lo split ----------------
__global__ void __launch_bounds__(256, 2) egemm_tc(const float* __restrict__ xexact)
{
    __shared__ float Ah[128][20], Al[128][20], Bh[128][20], Bl[128][20];

    int bz = blockIdx.z;
    int b = bz / ESPLIT, ks = bz - b * ESPLIT;
    const float* X = xexact + (size_t)b * Cc * NPIX;
    float* Cm = g_epart + (size_t)(ks * Bq + b) * Cc * Cc;
    const int KCH = NPIX / ESPLIT;
    int k0s = ks * KCH, k0e = k0s + KCH;

    int tid = threadIdx.x, lane = tid & 31, wid = tid >> 5;
    int wm = (wid & 1) * 64, wn = (wid >> 1) * 32;
    int row0 = blockIdx.y * 128, col0 = blockIdx.x * 128;
    int ar = tid >> 1, ak = (tid & 1) * 8;
    const float* Arx = X + (size_t)(row0 + ar) * NPIX + ak;
    const float* Brx = X + (size_t)(col0 + ar) * NPIX + ak;

    float acc[4][4][4];
#pragma unroll
    for (int i = 0; i < 4; i++)
#pragma unroll
        for (int j = 0; j < 4; j++)
#pragma unroll
            for (int r = 0; r < 4; r++) acc[i][j][r] = 0.f;

    for (int k0 = k0s; k0 < k0e; k0 += 16) {
        __syncthreads();
#pragma unroll
        for (int half = 0; half < 2; half++) {
            float4 va = *(const float4*)(Arx + k0 + half * 4);
            float4 vb4 = *(const float4*)(Brx + k0 + half * 4);
            float4 h, l;
            h.x = tf32r(va.x); l.x = tf32r(va.x - h.x);
            h.y = tf32r(va.y); l.y = tf32r(va.y - h.y);
            h.z = tf32r(va.z); l.z = tf32r(va.z - h.z);
            h.w = tf32r(va.w); l.w = tf32r(va.w - h.w);
            *(float4*)&Ah[ar][ak + half * 4] = h;
            *(float4*)&Al[ar][ak + half * 4] = l;
            h.x = tf32r(vb4.x); l.x = tf32r(vb4.x - h.x);
            h.y = tf32r(vb4.y); l.y = tf32r(vb4.y - h.y);
            h.z = tf32r(vb4.z); l.z = tf32r(vb4.z - h.z);
            h.w = tf32r(vb4.w); l.w = tf32r(vb4.w - h.w);
            *(float4*)&Bh[ar][ak + half * 4] = h;
            *(float4*)&Bl[ar][ak + half * 4] = l;
        }
        __syncthreads();
#pragma unroll
        for (int kk = 0; kk < 16; kk += 8) {
            int kq = kk + (lane & 3);
            int g4 = lane >> 2;
            uint32_t ah[4][4], al[4][4];
#pragma unroll
            for (int i = 0; i < 4; i++) {
                int m = wm + i * 16 + g4;
                ah[i][0] = __float_as_uint(Ah[m][kq]);
                ah[i][1] = __float_as_uint(Ah[m + 8][kq]);
                ah[i][2] = __float_as_uint(Ah[m][kq + 4]);
                ah[i][3] = __float_as_uint(Ah[m + 8][kq + 4]);
                al[i][0] = __float_as_uint(Al[m][kq]);
                al[i][1] = __float_as_uint(Al[m + 8][kq]);
                al[i][2] = __float_as_uint(Al[m][kq + 4]);
                al[i][3] = __float_as_uint(Al[m + 8][kq + 4]);
            }
#pragma unroll
            for (int j = 0; j < 4; j++) {
                int n = wn + j * 8 + g4;
                uint32_t bh[2], bl[2];
                bh[0] = __float_as_uint(Bh[n][kq]);
                bh[1] = __float_as_uint(Bh[n][kq + 4]);
                bl[0] = __float_as_uint(Bl[n][kq]);
                bl[1] = __float_as_uint(Bl[n][kq + 4]);
#pragma unroll
                for (int i = 0; i < 4; i++) {
                    mma1688(acc[i][j], ah[i], bh);
                    mma1688(acc[i][j], ah[i], bl);
                    mma1688(acc[i][j], al[i], bh);
                }
            }
        }
    }

#pragma unroll
    for (int i = 0; i < 4; i++) {
#pragma unroll
        for (int hh = 0; hh < 2; hh++) {
            int row = row0 + wm + i * 16 + (lane >> 2) + hh * 8;
#pragma unroll
            for (int j = 0; j < 4; j++) {
                int col = col0 + wn + j * 8 + (lane & 3) * 2;
                *(float2*)&Cm[(size_t)row * Cc + col] = make_float2(
                    acc[i][j][hh * 2 + 0], acc[i][j][hh * 2 + 1]);
            }
        }
    }
}

// ---------------- criss-cross attention ----------------
__global__ void __launch_bounds__(192) cca2_kernel(const float* __restrict__ gamma)
{
    extern __shared__ float sm[];
    float* e = sm;
    float* qs = sm + 192 * 96;
    float* ks_ = qs + 16 * 96;
    float* vr = ks_ + 16 * 96;

    int h = blockIdx.x, b = blockIdx.y;
    int tid = threadIdx.x;
    const float* qb = g_qkv + (size_t)b * 192 * NPIX;
    const float* kb = qb + (size_t)16 * NPIX;
    const float* vb = qb + (size_t)32 * NPIX;

    for (int idx = tid; idx < 16 * 96; idx += 192) {
        int c = idx / 96, w = idx - c * 96;
        qs[c * 96 + w] = qb[c * NPIX + h * Wd + w];
        ks_[c * 96 + w] = kb[c * NPIX + h * Wd + w];
    }
    __syncthreads();
    for (int idx = tid; idx < 96 * 96; idx += 192) {
        int s = idx / 96, w = idx - s * 96;
        float a = 0.f;
#pragma unroll
        for (int c = 0; c < 16; c++) a += qs[c * 96 + w] * ks_[c * 96 + s];
        e[(96 + s) * 96 + w] = a;
    }
    for (int idx = tid; idx < 96 * 96; idx += 192) {
        int s = idx / 96, w = idx - s * 96;
        float a = 0.f;
#pragma unroll
        for (int c = 0; c < 16; c++) a += qs[c * 96 + w] * kb[c * NPIX + s * Wd + w];
        e[s * 96 + w] = (s == h) ? -1e30f : a;
    }
    __syncthreads();
    if (tid < 96) {
        int w = tid;
        float M = -1e30f;
        for (int i = 0; i < 192; i++) M = fmaxf(M, e[i * 96 + w]);
        float S = 0.f;
        for (int i = 0; i < 192; i++) {
            float p = __expf(e[i * 96 + w] - M);
            e[i * 96 + w] = p; S += p;
        }
        float inv = 1.f / S;
        for (int i = 0; i < 192; i++) e[i * 96 + w] *= inv;
    }
    __syncthreads();
    int g = tid / 96;
    int w = tid - g * 96;
    float gam = __ldg(gamma);
    for (int cc = 0; cc < 64; cc++) {
        int c = g * 64 + cc;
        vr[g * 96 + w] = vb[(size_t)c * NPIX + h * Wd + w];
        __syncthreads();
        float oH = 0.f, oW = 0.f;
        const float* vcol = vb + (size_t)c * NPIX + w;
#pragma unroll 4
        for (int s = 0; s < 96; s++) {
            oH += vcol[s * Wd] * e[s * 96 + w];
            oW += vr[g * 96 + s] * e[(96 + s) * 96 + w];
        }
        size_t o = ((size_t)b * ICd + c) * NPIX + h * Wd + w;
        g_cca[o] = tf32r(gam * (oH + oW) + g_out1[o]);
        __syncthreads();
    }
}

// ---------------- CAM softmax (sums partials, scales by gamma_cam) ----------------
__global__ void __launch_bounds__(128) cam_softmax_kernel(const float* __restrict__ gma)
{
    int b = blockIdx.y, c = blockIdx.x;
    int t = threadIdx.x;
    __shared__ float red[4];
    float4 v = make_float4(0.f, 0.f, 0.f, 0.f);
#pragma unroll
    for (int s = 0; s < ESPLIT; s++) {
        const float4 p = *(const float4*)&g_epart[(((size_t)(s * Bq + b)) * Cc + c) * Cc + t * 4];
        v.x += p.x; v.y += p.y; v.z += p.z; v.w += p.w;
    }
    float lmn = fminf(fminf(v.x, v.y), fminf(v.z, v.w));
#pragma unroll
    for (int o = 16; o; o >>= 1) lmn = fminf(lmn, __shfl_xor_sync(0xffffffffu, lmn, o));
    if ((t & 31) == 0) red[t >> 5] = lmn;
    __syncthreads();
    float mn = fminf(fminf(red[0], red[1]), fminf(red[2], red[3]));
    __syncthreads();
    float4 p;
    p.x = __expf(mn - v.x); p.y = __expf(mn - v.y);
    p.z = __expf(mn - v.z); p.w = __expf(mn - v.w);
    float ls = p.x + p.y + p.z + p.w;
#pragma unroll
    for (int o = 16; o; o >>= 1) ls += __shfl_xor_sync(0xffffffffu, ls, o);
    if ((t & 31) == 0) red[t >> 5] = ls;
    __syncthreads();
    float gam = __ldg(gma);
    float inv = gam / (red[0] + red[1] + red[2] + red[3]);
    p.x = tf32r(p.x * inv); p.y = tf32r(p.y * inv);
    p.z = tf32r(p.z * inv); p.w = tf32r(p.w * inv);
    *(float4*)&g_energy[((size_t)b * Cc + c) * Cc + t * 4] = p;
}

// ---------------- launch ----------------
extern "C" void kernel_launch(void* const* d_in, const int* in_sizes, int n_in,
                              void* d_out, int out_size)
{
    const float* x        = (const float*)d_in[0];
    const float* conva_w  = (const float*)d_in[1];
    const float* bn1_s    = (const float*)d_in[2];
    const float* bn1_b    = (const float*)d_in[3];
    const float* bn1_m    = (const float*)d_in[4];
    const float* bn1_v    = (const float*)d_in[5];
    const float* wq       = (const float*)d_in[6];
    const float* bq       = (const float*)d_in[7];
    const float* wk       = (const float*)d_in[8];
    const float* bk       = (const float*)d_in[9];
    const float* wv       = (const float*)d_in[10];
    const float* bv       = (const float*)d_in[11];
    const float* gamma_cca= (const float*)d_in[12];
    const float* convb_w  = (const float*)d_in[13];
    const float* bn2_s    = (const float*)d_in[14];
    const float* bn2_b    = (const float*)d_in[15];
    const float* bn2_m    = (const float*)d_in[16];
    const float* bn2_v    = (const float*)d_in[17];
    const float* bot_w1   = (const float*)d_in[18];
    const float* bn3_s    = (const float*)d_in[19];
    const float* bn3_b    = (const float*)d_in[20];
    const float* bn3_m    = (const float*)d_in[21];
    const float* bn3_v    = (const float*)d_in[22];
    const float* bot_w2   = (const float*)d_in[23];
    const float* bot_b2   = (const float*)d_in[24];
    const float* gamma_cam= (const float*)d_in[25];
    float* out = (float*)d_out;

    float *p_xr, *p_cca, *p_b1, *p_wta, *p_wtb, *p_wt1, *p_out1, *p_out2;
    cudaGetSymbolAddress((void**)&p_xr, g_xr);
    cudaGetSymbolAddress((void**)&p_cca, g_cca);
    cudaGetSymbolAddress((void**)&p_b1, g_bott1);
    cudaGetSymbolAddress((void**)&p_wta, g_wta);
    cudaGetSymbolAddress((void**)&p_wtb, g_wtb);
    cudaGetSymbolAddress((void**)&p_wt1, g_wt1);
    cudaGetSymbolAddress((void**)&p_out1, g_out1);
    cudaGetSymbolAddress((void**)&p_out2, g_out2);

    cudaFuncSetAttribute(cca2_kernel, cudaFuncAttributeMaxDynamicSharedMemorySize, 90112);
    cudaFuncSetAttribute(conv_tc<9, true>, cudaFuncAttributeMaxDynamicSharedMemorySize, CONV_SMEM);
    cudaFuncSetAttribute(final_tc, cudaFuncAttributeMaxDynamicSharedMemorySize, CONV_SMEM);

    // prep
    roundcopy4<<<512, 256>>>(x, p_xr, Bq * Cc * NPIX / 4);
    prep_weights<<<512, 256>>>(conva_w, convb_w, bot_w1, bot_w2,
                               wq, bq, wk, bk, wv, bv);

    // conva 512->128 (+bn1+relu, rounded)
    conv_tc<9, true><<<dim3(36, 1, Bq), 256, CONV_SMEM>>>(
        p_xr, Cc, nullptr, 0, p_wta, ICd, p_out1,
        bn1_s, bn1_b, bn1_m, bn1_v);

    // qkv via tensor cores
    qkv_tc<<<dim3(36, 3, Bq), 256>>>();

    // cca
    cca2_kernel<<<dim3(Hd, Bq), 192, 90112>>>(gamma_cca);

    // convb 128->128 (+bn2+relu, rounded)   <- ncu launch index 5
    conv_tc<9, true><<<dim3(36, 1, Bq), 256, CONV_SMEM>>>(
        p_cca, ICd, nullptr, 0, p_wtb, ICd, p_out2,
        bn2_s, bn2_b, bn2_m, bn2_v);

    // bot conv1 concat(x,out2) 640->512 (+bn3+relu, rounded)
    conv_tc<9, true><<<dim3(36, 4, Bq), 256, CONV_SMEM>>>(
        p_xr, Cc, p_out2, ICd, p_wt1, Cc, p_b1,
        bn3_s, bn3_b, bn3_m, bn3_v);

    // CAM energy (3xTF32 TC, split-K, on-the-fly split)
    egemm_tc<<<dim3(Cc / 128, Cc / 128, Bq * ESPLIT), 256>>>(x);

    // CAM softmax -> g_energy (gamma-scaled attention)
    cam_softmax_kernel<<<dim3(Cc, Bq), 128>>>(gamma_cam);

    // final fused: out = W2*bott1 + b2 + att'*xr + x
    final_tc<<<dim3(36, 4, Bq), 256, CONV_SMEM>>>(x, bot_b2, out);
}